// round 9
// baseline (speedup 1.0000x reference)
#include <cuda_runtime.h>
#include <cuda_bf16.h>

#define NB 16
#define NL 1024
#define NH 8
#define NE 64
#define NM 64
#define NBH (NB*NH)
#define HE 512
#define SCALE_F 3.814697265625e-06f  // 1/(512*512)

typedef unsigned long long u64;
typedef unsigned u32;
typedef __nv_bfloat16 bf16;

// -------- scratch (static device globals) --------
static __device__ float g_Mt[4*NBH*NE*NE];                 // K-split x4 partials of M^T: [bh*4+ky][o][e]
static __device__ float g_ksp[4*NBH*NE];
static __device__ float g_vsp[4*NBH*NE];
static __device__ __align__(16) bf16 g_X[4*NBH*128*64];    // K-split x4 bf16 partials: [bh*4+ky][mr][e]
static __device__ __align__(16) bf16 g_Mtb[NBH*NE*NE];     // merged M^T bf16: [bh][o][e]
static __device__ float g_ks[NBH*NE];                      // merged ksum (fp32)
static __device__ float g_vs[NBH*NE];                      // merged vsum (fp32)
static __device__ __align__(16) bf16 g_Yt[NBH*64*128];     // [bh][o][mr]: 2m -> f*Yr, 2m+1 -> -f*Yi
static __device__ __align__(16) bf16 g_Tml[128*1024];      // [mr][l] (front fdft A tiles)
static __device__ uint4 g_Tfrag[8*8*8*32];                 // [ltile][wid][ks][lane] spec A-frags
static __device__ u32 g_WtR[NH*64*64*64];                  // [h][m][i][o] u32=(bf16 Wr, bf16 Wi)
static __device__ u32 g_WtI[NH*64*64*64];                  // [h][m][i][o] u32=(bf16 Wi, bf16 -Wr)

// ---------------- warp MMA helper ----------------
__device__ __forceinline__ void mma16816(float* d, const u32* a, const u32* b) {
    asm volatile(
        "mma.sync.aligned.m16n8k16.row.col.f32.bf16.bf16.f32 "
        "{%0,%1,%2,%3}, {%4,%5,%6,%7}, {%8,%9}, {%0,%1,%2,%3};"
        : "+f"(d[0]), "+f"(d[1]), "+f"(d[2]), "+f"(d[3])
        : "r"(a[0]), "r"(a[1]), "r"(a[2]), "r"(a[3]), "r"(b[0]), "r"(b[1]));
}
__device__ __forceinline__ u32 pkbf(float a, float b) {
    __nv_bfloat162 p = __floats2bfloat162_rn(a, b);   // a -> low
    return *(u32*)&p;
}

#define SPA 72    // bf16 pitch, K<=64 tiles: conflict-free frags
#define SPB 136   // bf16 pitch, K=128 tiles: conflict-free frags

// ===================== tables: Tml + Tfrag =====================
// blocks [0,128): Tml[mr][l]; blocks [128,192): Tfrag
__global__ void __launch_bounds__(256) k_tab() {
    const int t = threadIdx.x;
    if (blockIdx.x < 128) {
        int idx0 = blockIdx.x * 1024 + t;
        #pragma unroll
        for (int r = 0; r < 4; ++r) {
            int idx = idx0 + r * 256;          // 0..131071
            int mr = idx >> 10, l = idx & 1023;
            int m = mr >> 1;
            float s, c;
            sincospif((float)((m * l) & 1023) * (1.0f/512.0f), &s, &c);
            g_Tml[mr*1024 + l] = __float2bfloat16((mr & 1) ? s : c);
        }
    } else {
        int idx = (blockIdx.x - 128) * 256 + t;   // 0..16383
        int lt = idx >> 11, wid = (idx >> 8) & 7, ks = (idx >> 5) & 7, lane = idx & 31;
        int g = lane >> 2, tig = lane & 3;
        int r = lt*128 + wid*16 + g;
        int m = ks*8 + tig;
        float s0,c0,s1,c1,s2,c2,s3,c3;
        sincospif((float)((m*r)       & 1023) * (1.0f/512.0f), &s0, &c0);
        sincospif((float)((m*(r+8))   & 1023) * (1.0f/512.0f), &s1, &c1);
        sincospif((float)(((m+4)*r)   & 1023) * (1.0f/512.0f), &s2, &c2);
        sincospif((float)(((m+4)*(r+8)) & 1023) * (1.0f/512.0f), &s3, &c3);
        uint4 v;
        v.x = pkbf(c0, s0); v.y = pkbf(c1, s1); v.z = pkbf(c2, s2); v.w = pkbf(c3, s3);
        g_Tfrag[idx] = v;
    }
}

// ===================== merged front kernel: wt | stats | fdft =====================
#define FRONT_SMEM 33280

__global__ void __launch_bounds__(256, 4) k_front(const float* __restrict__ wre,
                                                  const float* __restrict__ wim,
                                                  const float* __restrict__ kin,
                                                  const float* __restrict__ vin,
                                                  const float* __restrict__ q) {
    extern __shared__ char dyns[];
    const int bx = blockIdx.x;
    const int t = threadIdx.x;

    if (bx < 512) {
        // ---------------- weight transpose ----------------
        float* smr = (float*)dyns;            // [64][65]
        float* smi = smr + 64*65;
        const int hi = bx;
        const int h = hi >> 6, i = hi & 63;
        const float* pr = wre + (size_t)hi * 4096;
        const float* pq = wim + (size_t)hi * 4096;
        #pragma unroll
        for (int it = 0; it < 4; ++it) {
            int idx = it * 256 + t;
            int o = idx >> 4, m4 = idx & 15;
            float4 vr = *(const float4*)(pr + o*64 + m4*4);
            float4 vi = *(const float4*)(pq + o*64 + m4*4);
            smr[o*65 + m4*4+0] = vr.x; smr[o*65 + m4*4+1] = vr.y;
            smr[o*65 + m4*4+2] = vr.z; smr[o*65 + m4*4+3] = vr.w;
            smi[o*65 + m4*4+0] = vi.x; smi[o*65 + m4*4+1] = vi.y;
            smi[o*65 + m4*4+2] = vi.z; smi[o*65 + m4*4+3] = vi.w;
        }
        __syncthreads();
        #pragma unroll
        for (int it = 0; it < 16; ++it) {
            int idx = it * 256 + t;
            int m = idx >> 6, o = idx & 63;
            float wr = smr[o*65 + m], wi = smi[o*65 + m];
            int dst = ((h*64 + m)*64 + i)*64 + o;
            g_WtR[dst] = pkbf(wr, wi);
            g_WtI[dst] = pkbf(wi, -wr);
        }
    } else if (bx < 1024) {
        // ---------------- stats: M^T = v^T k, K-split x4 ----------------
        bf16* sV = (bf16*)dyns;               // [64][SPA]
        bf16* sK = sV + 64*SPA;
        float* red = (float*)(sK + 64*SPA);   // [256]
        const int z = bx - 512;
        const int bh = z >> 2, ky = z & 3;
        const int b = bh >> 3, h = bh & 7;
        const int wid = t >> 5, lane = t & 31, g = lane >> 2, tig = lane & 3;
        const int ot = wid >> 1, eh = wid & 1;
        const int base = b * NL * HE + h * NE + ky * 256 * HE;
        float ka = 0.f, va = 0.f;
        float acc[4][4] = {};
        for (int c = 0; c < 4; ++c) {
            __syncthreads();
            #pragma unroll
            for (int it = 0; it < 16; ++it) {
                int idx = it * 256 + t;
                int s = idx >> 6, o = idx & 63;
                float vv = vin[base + (c*64 + s)*HE + o];
                float kv = kin[base + (c*64 + s)*HE + o];
                sV[o*SPA + s] = __float2bfloat16(vv);
                sK[o*SPA + s] = __float2bfloat16(kv);
                ka += kv; va += vv;
            }
            __syncthreads();
            #pragma unroll
            for (int ks = 0; ks < 4; ++ks) {
                const int k0 = ks * 16;
                u32 a[4];
                const bf16* ap = sV + (ot*16 + g)*SPA + k0 + tig*2;
                a[0] = *(const u32*)ap;
                a[1] = *(const u32*)(ap + 8*SPA);
                a[2] = *(const u32*)(ap + 8);
                a[3] = *(const u32*)(ap + 8*SPA + 8);
                #pragma unroll
                for (int n = 0; n < 4; ++n) {
                    const bf16* bp = sK + (eh*32 + n*8 + g)*SPA + k0 + tig*2;
                    u32 bfr[2] = {*(const u32*)bp, *(const u32*)(bp + 8)};
                    mma16816(acc[n], a, bfr);
                }
            }
        }
        float* Mo = g_Mt + (bh*4 + ky) * 4096;
        const int o0 = ot*16 + g;
        #pragma unroll
        for (int n = 0; n < 4; ++n) {
            int col = eh*32 + n*8 + tig*2;
            *(float2*)(Mo + o0*64 + col)     = make_float2(acc[n][0], acc[n][1]);
            *(float2*)(Mo + (o0+8)*64 + col) = make_float2(acc[n][2], acc[n][3]);
        }
        red[t] = ka; __syncthreads();
        if (t < 64) g_ksp[(bh*4+ky)*64 + t] = red[t] + red[t+64] + red[t+128] + red[t+192];
        __syncthreads();
        red[t] = va; __syncthreads();
        if (t < 64) g_vsp[(bh*4+ky)*64 + t] = red[t] + red[t+64] + red[t+128] + red[t+192];
    } else {
        // ---------------- forward DFT, K-split x4, bf16 X partials ----------------
        bf16* sA = (bf16*)dyns;               // [128][SPA]
        bf16* sB = sA + 128*SPA;              // [64][SPA]
        const int z = bx - 1024;
        const int bh = z >> 2, ky = z & 3;
        const int b = bh >> 3, h = bh & 7;
        const int wid = t >> 5, lane = t & 31, g = lane >> 2, tig = lane & 3;
        const int base = b * NL * HE + h * NE;
        float acc[8][4] = {};
        for (int c = 0; c < 4; ++c) {
            const int cc = ky*4 + c;
            __syncthreads();
            #pragma unroll
            for (int it = 0; it < 16; ++it) {
                int idx = it * 256 + t;
                int row = idx >> 5, w = idx & 31;
                ((u32*)(sA + row*SPA))[w] = ((const u32*)(g_Tml + row*1024 + cc*64))[w];
            }
            #pragma unroll
            for (int it = 0; it < 16; ++it) {
                int idx = it * 256 + t;
                int l = idx >> 6, e = idx & 63;
                sB[e*SPA + l] = __float2bfloat16(q[base + (cc*64 + l)*HE + e]);
            }
            __syncthreads();
            #pragma unroll
            for (int ks = 0; ks < 4; ++ks) {
                const int k0 = ks * 16;
                u32 a[4];
                const bf16* ap = sA + (wid*16 + g)*SPA + k0 + tig*2;
                a[0] = *(const u32*)ap;
                a[1] = *(const u32*)(ap + 8*SPA);
                a[2] = *(const u32*)(ap + 8);
                a[3] = *(const u32*)(ap + 8*SPA + 8);
                #pragma unroll
                for (int n = 0; n < 8; ++n) {
                    const bf16* bp = sB + (n*8 + g)*SPA + k0 + tig*2;
                    u32 bfr[2] = {*(const u32*)bp, *(const u32*)(bp + 8)};
                    mma16816(acc[n], a, bfr);
                }
            }
        }
        bf16* Xb = g_X + (bh*4 + ky) * 8192;
        const int m0 = wid*16 + g;
        #pragma unroll
        for (int n = 0; n < 8; ++n) {
            int col = n*8 + tig*2;
            *(u32*)(Xb + m0*64 + col)     = pkbf(acc[n][0], acc[n][1]);
            *(u32*)(Xb + (m0+8)*64 + col) = pkbf(acc[n][2], acc[n][3]);
        }
    }
}

// ===================== kernel C: complex mix via MMA | Mt merge =====================
// blocks [0,512): mix per (h,m); blocks [512,640): merge Mt/ksum/vsum partials
__global__ void __launch_bounds__(128) k_mix_mma() {
    __shared__ bf16 sA[16][SPB];
    __shared__ bf16 sBr[64][SPB];
    __shared__ bf16 sBi[64][SPB];
    const int bx = blockIdx.x;
    const int t = threadIdx.x;
    if (bx >= 512) {
        const int bh = bx - 512;
        const float* Mp = g_Mt + bh*4*4096;
        for (int idx = t; idx < 4096; idx += 128) {
            float s = Mp[idx] + Mp[4096 + idx] + Mp[8192 + idx] + Mp[12288 + idx];
            g_Mtb[bh*4096 + idx] = __float2bfloat16(s);
        }
        if (t < 64) {
            const float* kp = g_ksp + bh*4*64;
            const float* vp = g_vsp + bh*4*64;
            g_ks[bh*64 + t] = kp[t] + kp[64+t] + kp[128+t] + kp[192+t];
            g_vs[bh*64 + t] = vp[t] + vp[64+t] + vp[128+t] + vp[192+t];
        }
        return;
    }
    const int h = bx >> 6, m = bx & 63;
    const int wid = t >> 5, lane = t & 31, g = lane >> 2, tig = lane & 3;
    #pragma unroll
    for (int it = 0; it < 8; ++it) {
        int idx = it * 128 + t;
        int bb = idx >> 6, i = idx & 63;
        const bf16* X0 = g_X + ((bb*8 + h)*4)*8192 + (2*m)*64;
        float xc = 0.f, xs = 0.f;
        #pragma unroll
        for (int ky = 0; ky < 4; ++ky) {
            xc += __bfloat162float(X0[ky*8192 + i]);
            xs += __bfloat162float(X0[ky*8192 + 64 + i]);
        }
        *(u32*)&sA[bb][2*i] = pkbf(xc, xs);
    }
    const u32* WR = g_WtR + (h*64 + m)*4096;
    const u32* WI = g_WtI + (h*64 + m)*4096;
    #pragma unroll
    for (int it = 0; it < 32; ++it) {
        int idx = it * 128 + t;
        int i = idx >> 6, o = idx & 63;
        *(u32*)&sBr[o][2*i] = WR[i*64 + o];
        *(u32*)&sBi[o][2*i] = WI[i*64 + o];
    }
    __syncthreads();
    float acc[2][2][4] = {};
    #pragma unroll
    for (int ks = 0; ks < 8; ++ks) {
        const int k0 = ks * 16;
        u32 a[4];
        const bf16* ap = &sA[g][k0 + tig*2];
        a[0] = *(const u32*)ap;
        a[1] = *(const u32*)(ap + 8*SPB);
        a[2] = *(const u32*)(ap + 8);
        a[3] = *(const u32*)(ap + 8*SPB + 8);
        #pragma unroll
        for (int n = 0; n < 2; ++n) {
            int o = wid*16 + n*8 + g;
            const bf16* brp = &sBr[o][k0 + tig*2];
            u32 br[2] = {*(const u32*)brp, *(const u32*)(brp + 8)};
            mma16816(acc[0][n], a, br);
            const bf16* bip = &sBi[o][k0 + tig*2];
            u32 bi2[2] = {*(const u32*)bip, *(const u32*)(bip + 8)};
            mma16816(acc[1][n], a, bi2);
        }
    }
    const float f = (m == 0 ? 1.0f : 2.0f) * (1.0f / 2048.0f);
    u32* Yt32 = (u32*)g_Yt;
    #pragma unroll
    for (int n = 0; n < 2; ++n)
        #pragma unroll
        for (int cc = 0; cc < 2; ++cc) {
            int o = wid*16 + n*8 + tig*2 + cc;
            Yt32[((g*8 + h)*64 + o)*64 + m]     = pkbf(f*acc[0][n][cc],   -f*acc[1][n][cc]);
            Yt32[(((g+8)*8 + h)*64 + o)*64 + m] = pkbf(f*acc[0][n][cc+2], -f*acc[1][n][cc+2]);
        }
}

// ===================== fused D: local attention + inverse DFT =====================
#define FQ_OFF  0
#define FM_OFF  18432
#define FY_OFF  28800
#define FV_OFF  46208
#define FUSED_SMEM 46464

__global__ void __launch_bounds__(256, 2) k_fused(const float* __restrict__ q,
                                                  float* __restrict__ out) {
    extern __shared__ char dyns[];
    bf16*  sQ  = (bf16*)(dyns + FQ_OFF);    // [128][SPA] rows l
    bf16*  sMt = (bf16*)(dyns + FM_OFF);    // [72][SPA]  rows o (64=ksum, 65-71=0)
    bf16*  sY  = (bf16*)(dyns + FY_OFF);    // [64][SPB]  rows o, k=mr
    float* svs = (float*)(dyns + FV_OFF);
    const int bh = blockIdx.x;
    const int b = bh >> 3, h = bh & 7;
    const int l0 = blockIdx.y * 128;
    const int t = threadIdx.x;
    const int wid = t >> 5, lane = t & 31, g = lane >> 2, tig = lane & 3;
    const int base = b * NL * HE + h * NE;

    #pragma unroll
    for (int it = 0; it < 16; ++it) {
        int idx = it * 256 + t;
        int l = idx >> 5, e2 = idx & 31;
        float2 qv = *(const float2*)(q + base + (l0 + l)*HE + e2*2);
        *(u32*)(sQ + l*SPA + e2*2) = pkbf(qv.x, qv.y);
    }
    #pragma unroll
    for (int it = 0; it < 8; ++it) {
        int idx = it * 256 + t;
        int o = idx >> 5, w = idx & 31;
        ((u32*)(sMt + o*SPA))[w] = ((const u32*)(g_Mtb + bh*4096 + o*64))[w];
    }
    if (t < 64) {
        sMt[64*SPA + t] = __float2bfloat16(g_ks[bh*64 + t]);
        svs[t] = g_vs[bh*64 + t];
    }
    for (int idx = t; idx < 7*SPA; idx += 256)
        sMt[65*SPA + idx] = __float2bfloat16(0.f);
    #pragma unroll
    for (int it = 0; it < 16; ++it) {
        int idx = it * 256 + t;
        int o = idx >> 6, w = idx & 63;
        ((u32*)(sY + o*SPB))[w] = ((const u32*)(g_Yt + bh*8192 + o*128))[w];
    }
    __syncthreads();

    float accL[9][4] = {};
    float accS[8][4] = {};
    // local: K=64 (A from sQ, B from sMt)
    #pragma unroll
    for (int ks = 0; ks < 4; ++ks) {
        const int k0 = ks * 16;
        u32 a[4];
        const bf16* ap = sQ + (wid*16 + g)*SPA + k0 + tig*2;
        a[0] = *(const u32*)ap;
        a[1] = *(const u32*)(ap + 8*SPA);
        a[2] = *(const u32*)(ap + 8);
        a[3] = *(const u32*)(ap + 8*SPA + 8);
        #pragma unroll
        for (int n = 0; n < 9; ++n) {
            const bf16* bp = sMt + (n*8 + g)*SPA + k0 + tig*2;
            u32 bfr[2] = {*(const u32*)bp, *(const u32*)(bp + 8)};
            mma16816(accL[n], a, bfr);
        }
    }
    // spec: K=128 (A-frags direct from g_Tfrag, B from sY)
    {
        const uint4* tf = g_Tfrag + ((blockIdx.y*8 + wid)*8)*32 + lane;
        #pragma unroll
        for (int ks = 0; ks < 8; ++ks) {
            const int k0 = ks * 16;
            uint4 av = tf[ks*32];
            u32 a[4] = {av.x, av.y, av.z, av.w};
            #pragma unroll
            for (int n = 0; n < 8; ++n) {
                const bf16* bp = sY + (n*8 + g)*SPB + k0 + tig*2;
                u32 bfr[2] = {*(const u32*)bp, *(const u32*)(bp + 8)};
                mma16816(accS[n], a, bfr);
            }
        }
    }
    const int r0 = wid*16 + g;
    float z0 = __shfl_sync(0xffffffffu, accL[8][0], lane & ~3);
    float z1 = __shfl_sync(0xffffffffu, accL[8][2], lane & ~3);
    float inv0 = 0.5f / (1024.0f + SCALE_F * z0);
    float inv1 = 0.5f / (1024.0f + SCALE_F * z1);
    #pragma unroll
    for (int n = 0; n < 8; ++n) {
        int col = n*8 + tig*2;
        float2 o0 = make_float2(
            (svs[col]   + SCALE_F*accL[n][0]) * inv0 + accS[n][0],
            (svs[col+1] + SCALE_F*accL[n][1]) * inv0 + accS[n][1]);
        *(float2*)(out + (b*NL + l0 + r0)*HE + h*NE + col) = o0;
        float2 o1 = make_float2(
            (svs[col]   + SCALE_F*accL[n][2]) * inv1 + accS[n][2],
            (svs[col+1] + SCALE_F*accL[n][3]) * inv1 + accS[n][3]);
        *(float2*)(out + (b*NL + l0 + r0 + 8)*HE + h*NE + col) = o1;
    }
}

// ===================== launch =====================
extern "C" void kernel_launch(void* const* d_in, const int* in_sizes, int n_in,
                              void* d_out, int out_size) {
    (void)in_sizes; (void)n_in; (void)out_size;
    const float* q   = (const float*)d_in[0];
    const float* k   = (const float*)d_in[1];
    const float* v   = (const float*)d_in[2];
    // d_in[3] = mask (present -> reference applies no masking); unused
    const float* wre = (const float*)d_in[4];
    const float* wim = (const float*)d_in[5];
    float* out = (float*)d_out;

    static int smem_set = 0;
    if (!smem_set) {
        cudaFuncSetAttribute(k_fused, cudaFuncAttributeMaxDynamicSharedMemorySize, FUSED_SMEM);
        smem_set = 1;
    }

    k_tab    <<<192, 256>>>();
    k_front  <<<1536, 256, FRONT_SMEM>>>(wre, wim, k, v, q);
    k_mix_mma<<<640, 128>>>();
    k_fused  <<<dim3(NBH, 8), 256, FUSED_SMEM>>>(q, out);
}

// round 10
// speedup vs baseline: 1.0479x; 1.0479x over previous
#include <cuda_runtime.h>
#include <cuda_bf16.h>

#define NB 16
#define NL 1024
#define NH 8
#define NE 64
#define NM 64
#define NBH (NB*NH)
#define HE 512
#define SCALE_F 3.814697265625e-06f  // 1/(512*512)

typedef unsigned long long u64;
typedef unsigned u32;
typedef __nv_bfloat16 bf16;

// -------- scratch (static device globals) --------
static __device__ float g_Mt[4*NBH*NE*NE];                 // K-split x4 partials of M^T: [bh*4+ky][o][e]
static __device__ float g_ksp[4*NBH*NE];
static __device__ float g_vsp[4*NBH*NE];
static __device__ __align__(16) bf16 g_X[4*NBH*128*64];    // K-split x4 bf16 partials: [bh*4+ky][mr][e]
static __device__ __align__(16) bf16 g_Mtb[NBH*NE*NE];     // merged M^T bf16: [bh][o][e]
static __device__ float g_ks[NBH*NE];                      // merged ksum (fp32)
static __device__ float g_vs[NBH*NE];                      // merged vsum (fp32)
static __device__ __align__(16) bf16 g_Yt[NBH*64*128];     // [bh][o][mr]: 2m -> f*Yr, 2m+1 -> -f*Yi
static __device__ __align__(16) bf16 g_Tml[128*1024];      // [mr][l] (front fdft A tiles)
static __device__ uint4 g_Tfrag[8*8*8*32];                 // [ltile][wid][ks][lane] spec A-frags
static __device__ u32 g_WtR[NH*64*64*64];                  // [h][m][i][o] u32=(bf16 Wr, bf16 Wi)
static __device__ u32 g_WtI[NH*64*64*64];                  // [h][m][i][o] u32=(bf16 Wi, bf16 -Wr)

// ---------------- warp MMA helper ----------------
__device__ __forceinline__ void mma16816(float* d, const u32* a, const u32* b) {
    asm volatile(
        "mma.sync.aligned.m16n8k16.row.col.f32.bf16.bf16.f32 "
        "{%0,%1,%2,%3}, {%4,%5,%6,%7}, {%8,%9}, {%0,%1,%2,%3};"
        : "+f"(d[0]), "+f"(d[1]), "+f"(d[2]), "+f"(d[3])
        : "r"(a[0]), "r"(a[1]), "r"(a[2]), "r"(a[3]), "r"(b[0]), "r"(b[1]));
}
__device__ __forceinline__ u32 pkbf(float a, float b) {
    __nv_bfloat162 p = __floats2bfloat162_rn(a, b);   // a -> low
    return *(u32*)&p;
}

#define SPA 72    // bf16 pitch, K<=64 tiles: conflict-free frags
#define SPB 136   // bf16 pitch, K=128 tiles: conflict-free frags

// ===================== table: Tml via smem cos/sin lookup =====================
__global__ void __launch_bounds__(256) k_tab() {
    __shared__ float2 cs[1024];
    const int t = threadIdx.x;
    #pragma unroll
    for (int r = 0; r < 4; ++r) {
        int j = r*256 + t;
        float s, c;
        sincospif((float)j * (1.0f/512.0f), &s, &c);
        cs[j] = make_float2(c, s);
    }
    __syncthreads();
    #pragma unroll
    for (int r = 0; r < 16; ++r) {
        int idx = r*256 + t;                       // 0..4095
        int mr = blockIdx.x*4 + (idx >> 10), l = idx & 1023;
        int m = mr >> 1;
        float2 v = cs[(m*l) & 1023];
        g_Tml[mr*1024 + l] = __float2bfloat16((mr & 1) ? v.y : v.x);
    }
}

// ===================== merged front kernel: wt | stats | fdft =====================
#define FRONT_SMEM 33280

__global__ void __launch_bounds__(256, 3) k_front(const float* __restrict__ wre,
                                                  const float* __restrict__ wim,
                                                  const float* __restrict__ kin,
                                                  const float* __restrict__ vin,
                                                  const float* __restrict__ q) {
    extern __shared__ char dyns[];
    const int bx = blockIdx.x;
    const int t = threadIdx.x;

    if (bx < 512) {
        // ---------------- weight transpose ----------------
        float* smr = (float*)dyns;            // [64][65]
        float* smi = smr + 64*65;
        const int hi = bx;
        const int h = hi >> 6, i = hi & 63;
        const float* pr = wre + (size_t)hi * 4096;
        const float* pq = wim + (size_t)hi * 4096;
        #pragma unroll
        for (int it = 0; it < 4; ++it) {
            int idx = it * 256 + t;
            int o = idx >> 4, m4 = idx & 15;
            float4 vr = *(const float4*)(pr + o*64 + m4*4);
            float4 vi = *(const float4*)(pq + o*64 + m4*4);
            smr[o*65 + m4*4+0] = vr.x; smr[o*65 + m4*4+1] = vr.y;
            smr[o*65 + m4*4+2] = vr.z; smr[o*65 + m4*4+3] = vr.w;
            smi[o*65 + m4*4+0] = vi.x; smi[o*65 + m4*4+1] = vi.y;
            smi[o*65 + m4*4+2] = vi.z; smi[o*65 + m4*4+3] = vi.w;
        }
        __syncthreads();
        #pragma unroll
        for (int it = 0; it < 16; ++it) {
            int idx = it * 256 + t;
            int m = idx >> 6, o = idx & 63;
            float wr = smr[o*65 + m], wi = smi[o*65 + m];
            int dst = ((h*64 + m)*64 + i)*64 + o;
            g_WtR[dst] = pkbf(wr, wi);
            g_WtI[dst] = pkbf(wi, -wr);
        }
    } else if (bx < 1024) {
        // ---------------- stats: M^T = v^T k, K-split x4, reg-prefetch pipeline ----------------
        bf16* sV = (bf16*)dyns;               // [64][SPA]
        bf16* sK = sV + 64*SPA;
        float* red = (float*)(sK + 64*SPA);   // [256]
        const int z = bx - 512;
        const int bh = z >> 2, ky = z & 3;
        const int b = bh >> 3, h = bh & 7;
        const int wid = t >> 5, lane = t & 31, g = lane >> 2, tig = lane & 3;
        const int ot = wid >> 1, eh = wid & 1;
        const int base = b * NL * HE + h * NE + ky * 256 * HE;
        const int s0 = t >> 6, o0 = t & 63;   // per-it stride: s += 4
        float pk[16], pv[16];
        #pragma unroll
        for (int it = 0; it < 16; ++it) {
            int off = base + (s0 + it*4)*HE + o0;
            pk[it] = kin[off];
            pv[it] = vin[off];
        }
        float ka = 0.f, va = 0.f;
        float acc[4][4] = {};
        for (int c = 0; c < 4; ++c) {
            __syncthreads();
            #pragma unroll
            for (int it = 0; it < 16; ++it) {
                int s = s0 + it*4;
                sK[o0*SPA + s] = __float2bfloat16(pk[it]);
                sV[o0*SPA + s] = __float2bfloat16(pv[it]);
                ka += pk[it]; va += pv[it];
            }
            if (c < 3) {
                #pragma unroll
                for (int it = 0; it < 16; ++it) {
                    int off = base + ((c+1)*64 + s0 + it*4)*HE + o0;
                    pk[it] = kin[off];
                    pv[it] = vin[off];
                }
            }
            __syncthreads();
            #pragma unroll
            for (int ks = 0; ks < 4; ++ks) {
                const int k0 = ks * 16;
                u32 a[4];
                const bf16* ap = sV + (ot*16 + g)*SPA + k0 + tig*2;
                a[0] = *(const u32*)ap;
                a[1] = *(const u32*)(ap + 8*SPA);
                a[2] = *(const u32*)(ap + 8);
                a[3] = *(const u32*)(ap + 8*SPA + 8);
                #pragma unroll
                for (int n = 0; n < 4; ++n) {
                    const bf16* bp = sK + (eh*32 + n*8 + g)*SPA + k0 + tig*2;
                    u32 bfr[2] = {*(const u32*)bp, *(const u32*)(bp + 8)};
                    mma16816(acc[n], a, bfr);
                }
            }
        }
        float* Mo = g_Mt + (bh*4 + ky) * 4096;
        const int oo0 = ot*16 + g;
        #pragma unroll
        for (int n = 0; n < 4; ++n) {
            int col = eh*32 + n*8 + tig*2;
            *(float2*)(Mo + oo0*64 + col)     = make_float2(acc[n][0], acc[n][1]);
            *(float2*)(Mo + (oo0+8)*64 + col) = make_float2(acc[n][2], acc[n][3]);
        }
        red[t] = ka; __syncthreads();
        if (t < 64) g_ksp[(bh*4+ky)*64 + t] = red[t] + red[t+64] + red[t+128] + red[t+192];
        __syncthreads();
        red[t] = va; __syncthreads();
        if (t < 64) g_vsp[(bh*4+ky)*64 + t] = red[t] + red[t+64] + red[t+128] + red[t+192];
    } else {
        // ---------------- forward DFT, K-split x4, reg-prefetch pipeline ----------------
        bf16* sA = (bf16*)dyns;               // [128][SPA]
        bf16* sB = sA + 128*SPA;              // [64][SPA]
        const int z = bx - 1024;
        const int bh = z >> 2, ky = z & 3;
        const int b = bh >> 3, h = bh & 7;
        const int wid = t >> 5, lane = t & 31, g = lane >> 2, tig = lane & 3;
        const int base = b * NL * HE + h * NE;
        const int l00 = t >> 6, e0 = t & 63;  // per-it stride: l += 4
        float pq[16];
        #pragma unroll
        for (int it = 0; it < 16; ++it)
            pq[it] = q[base + (ky*256 + l00 + it*4)*HE + e0];
        float acc[8][4] = {};
        for (int c = 0; c < 4; ++c) {
            const int cc = ky*4 + c;
            __syncthreads();
            #pragma unroll
            for (int it = 0; it < 16; ++it) {
                int idx = it * 256 + t;
                int row = idx >> 5, w = idx & 31;
                ((u32*)(sA + row*SPA))[w] = ((const u32*)(g_Tml + row*1024 + cc*64))[w];
            }
            #pragma unroll
            for (int it = 0; it < 16; ++it)
                sB[e0*SPA + (l00 + it*4)] = __float2bfloat16(pq[it]);
            if (c < 3) {
                #pragma unroll
                for (int it = 0; it < 16; ++it)
                    pq[it] = q[base + (ky*256 + (c+1)*64 + l00 + it*4)*HE + e0];
            }
            __syncthreads();
            #pragma unroll
            for (int ks = 0; ks < 4; ++ks) {
                const int k0 = ks * 16;
                u32 a[4];
                const bf16* ap = sA + (wid*16 + g)*SPA + k0 + tig*2;
                a[0] = *(const u32*)ap;
                a[1] = *(const u32*)(ap + 8*SPA);
                a[2] = *(const u32*)(ap + 8);
                a[3] = *(const u32*)(ap + 8*SPA + 8);
                #pragma unroll
                for (int n = 0; n < 8; ++n) {
                    const bf16* bp = sB + (n*8 + g)*SPA + k0 + tig*2;
                    u32 bfr[2] = {*(const u32*)bp, *(const u32*)(bp + 8)};
                    mma16816(acc[n], a, bfr);
                }
            }
        }
        bf16* Xb = g_X + (bh*4 + ky) * 8192;
        const int m0 = wid*16 + g;
        #pragma unroll
        for (int n = 0; n < 8; ++n) {
            int col = n*8 + tig*2;
            *(u32*)(Xb + m0*64 + col)     = pkbf(acc[n][0], acc[n][1]);
            *(u32*)(Xb + (m0+8)*64 + col) = pkbf(acc[n][2], acc[n][3]);
        }
    }
}

// ===================== kernel C: mix | Mt merge | Tfrag gen =====================
// blocks [0,512): mix per (h,m); [512,640): Mt/ksum/vsum merge; [640,704): Tfrag
__global__ void __launch_bounds__(128) k_mix_mma() {
    __shared__ bf16 sA[16][SPB];
    __shared__ bf16 sBr[64][SPB];
    __shared__ bf16 sBi[64][SPB];
    const int bx = blockIdx.x;
    const int t = threadIdx.x;
    if (bx >= 640) {
        #pragma unroll
        for (int r = 0; r < 2; ++r) {
            int idx = (bx - 640)*256 + r*128 + t;   // 0..16383
            int lt = idx >> 11, wid = (idx >> 8) & 7, ks = (idx >> 5) & 7, lane = idx & 31;
            int g = lane >> 2, tig = lane & 3;
            int rr = lt*128 + wid*16 + g;
            int m = ks*8 + tig;
            float s0,c0,s1,c1,s2,c2,s3,c3;
            sincospif((float)((m*rr)        & 1023) * (1.0f/512.0f), &s0, &c0);
            sincospif((float)((m*(rr+8))    & 1023) * (1.0f/512.0f), &s1, &c1);
            sincospif((float)(((m+4)*rr)    & 1023) * (1.0f/512.0f), &s2, &c2);
            sincospif((float)(((m+4)*(rr+8))& 1023) * (1.0f/512.0f), &s3, &c3);
            uint4 v;
            v.x = pkbf(c0, s0); v.y = pkbf(c1, s1); v.z = pkbf(c2, s2); v.w = pkbf(c3, s3);
            g_Tfrag[idx] = v;
        }
        return;
    }
    if (bx >= 512) {
        const int bh = bx - 512;
        const float* Mp = g_Mt + bh*4*4096;
        for (int idx = t; idx < 4096; idx += 128) {
            float s = Mp[idx] + Mp[4096 + idx] + Mp[8192 + idx] + Mp[12288 + idx];
            g_Mtb[bh*4096 + idx] = __float2bfloat16(s);
        }
        if (t < 64) {
            const float* kp = g_ksp + bh*4*64;
            const float* vp = g_vsp + bh*4*64;
            g_ks[bh*64 + t] = kp[t] + kp[64+t] + kp[128+t] + kp[192+t];
            g_vs[bh*64 + t] = vp[t] + vp[64+t] + vp[128+t] + vp[192+t];
        }
        return;
    }
    const int h = bx >> 6, m = bx & 63;
    const int wid = t >> 5, lane = t & 31, g = lane >> 2, tig = lane & 3;
    #pragma unroll
    for (int it = 0; it < 8; ++it) {
        int idx = it * 128 + t;
        int bb = idx >> 6, i = idx & 63;
        const bf16* X0 = g_X + ((bb*8 + h)*4)*8192 + (2*m)*64;
        float xc = 0.f, xs = 0.f;
        #pragma unroll
        for (int ky = 0; ky < 4; ++ky) {
            xc += __bfloat162float(X0[ky*8192 + i]);
            xs += __bfloat162float(X0[ky*8192 + 64 + i]);
        }
        *(u32*)&sA[bb][2*i] = pkbf(xc, xs);
    }
    const u32* WR = g_WtR + (h*64 + m)*4096;
    const u32* WI = g_WtI + (h*64 + m)*4096;
    #pragma unroll
    for (int it = 0; it < 32; ++it) {
        int idx = it * 128 + t;
        int i = idx >> 6, o = idx & 63;
        *(u32*)&sBr[o][2*i] = WR[i*64 + o];
        *(u32*)&sBi[o][2*i] = WI[i*64 + o];
    }
    __syncthreads();
    float acc[2][2][4] = {};
    #pragma unroll
    for (int ks = 0; ks < 8; ++ks) {
        const int k0 = ks * 16;
        u32 a[4];
        const bf16* ap = &sA[g][k0 + tig*2];
        a[0] = *(const u32*)ap;
        a[1] = *(const u32*)(ap + 8*SPB);
        a[2] = *(const u32*)(ap + 8);
        a[3] = *(const u32*)(ap + 8*SPB + 8);
        #pragma unroll
        for (int n = 0; n < 2; ++n) {
            int o = wid*16 + n*8 + g;
            const bf16* brp = &sBr[o][k0 + tig*2];
            u32 br[2] = {*(const u32*)brp, *(const u32*)(brp + 8)};
            mma16816(acc[0][n], a, br);
            const bf16* bip = &sBi[o][k0 + tig*2];
            u32 bi2[2] = {*(const u32*)bip, *(const u32*)(bip + 8)};
            mma16816(acc[1][n], a, bi2);
        }
    }
    const float f = (m == 0 ? 1.0f : 2.0f) * (1.0f / 2048.0f);
    u32* Yt32 = (u32*)g_Yt;
    #pragma unroll
    for (int n = 0; n < 2; ++n)
        #pragma unroll
        for (int cc = 0; cc < 2; ++cc) {
            int o = wid*16 + n*8 + tig*2 + cc;
            Yt32[((g*8 + h)*64 + o)*64 + m]     = pkbf(f*acc[0][n][cc],   -f*acc[1][n][cc]);
            Yt32[(((g+8)*8 + h)*64 + o)*64 + m] = pkbf(f*acc[0][n][cc+2], -f*acc[1][n][cc+2]);
        }
}

// ===================== fused D: local attention + inverse DFT, 2 l-tiles/block =====================
#define FQ_OFF  0
#define FM_OFF  18432
#define FY_OFF  28800
#define FV_OFF  46208
#define FUSED_SMEM 46464

__global__ void __launch_bounds__(256, 2) k_fused(const float* __restrict__ q,
                                                  float* __restrict__ out) {
    extern __shared__ char dyns[];
    bf16*  sQ  = (bf16*)(dyns + FQ_OFF);    // [128][SPA] rows l
    bf16*  sMt = (bf16*)(dyns + FM_OFF);    // [72][SPA]  rows o (64=ksum, 65-71=0)
    bf16*  sY  = (bf16*)(dyns + FY_OFF);    // [64][SPB]  rows o, k=mr
    float* svs = (float*)(dyns + FV_OFF);
    const int bh = blockIdx.x;
    const int b = bh >> 3, h = bh & 7;
    const int t = threadIdx.x;
    const int wid = t >> 5, lane = t & 31, g = lane >> 2, tig = lane & 3;
    const int base = b * NL * HE + h * NE;

    // stage per-bh data once
    #pragma unroll
    for (int it = 0; it < 8; ++it) {
        int idx = it * 256 + t;
        int o = idx >> 5, w = idx & 31;
        ((u32*)(sMt + o*SPA))[w] = ((const u32*)(g_Mtb + bh*4096 + o*64))[w];
    }
    if (t < 64) {
        sMt[64*SPA + t] = __float2bfloat16(g_ks[bh*64 + t]);
        svs[t] = g_vs[bh*64 + t];
    }
    for (int idx = t; idx < 7*SPA; idx += 256)
        sMt[65*SPA + idx] = __float2bfloat16(0.f);
    #pragma unroll
    for (int it = 0; it < 16; ++it) {
        int idx = it * 256 + t;
        int o = idx >> 6, w = idx & 63;
        ((u32*)(sY + o*SPB))[w] = ((const u32*)(g_Yt + bh*8192 + o*128))[w];
    }
    // first tile's q
    {
        const int l0 = blockIdx.y * 256;
        #pragma unroll
        for (int it = 0; it < 16; ++it) {
            int idx = it * 256 + t;
            int l = idx >> 5, e2 = idx & 31;
            float2 qv = *(const float2*)(q + base + (l0 + l)*HE + e2*2);
            *(u32*)(sQ + l*SPA + e2*2) = pkbf(qv.x, qv.y);
        }
    }
    __syncthreads();

    for (int ti = 0; ti < 2; ++ti) {
        const int lt = blockIdx.y*2 + ti;
        const int l0 = lt * 128;
        float accL[9][4] = {};
        float accS[8][4] = {};
        // local: K=64 (A from sQ, B from sMt)
        #pragma unroll
        for (int ks = 0; ks < 4; ++ks) {
            const int k0 = ks * 16;
            u32 a[4];
            const bf16* ap = sQ + (wid*16 + g)*SPA + k0 + tig*2;
            a[0] = *(const u32*)ap;
            a[1] = *(const u32*)(ap + 8*SPA);
            a[2] = *(const u32*)(ap + 8);
            a[3] = *(const u32*)(ap + 8*SPA + 8);
            #pragma unroll
            for (int n = 0; n < 9; ++n) {
                const bf16* bp = sMt + (n*8 + g)*SPA + k0 + tig*2;
                u32 bfr[2] = {*(const u32*)bp, *(const u32*)(bp + 8)};
                mma16816(accL[n], a, bfr);
            }
        }
        // spec: K=128 (A-frags direct from g_Tfrag, B from sY)
        {
            const uint4* tf = g_Tfrag + ((lt*8 + wid)*8)*32 + lane;
            #pragma unroll
            for (int ks = 0; ks < 8; ++ks) {
                const int k0 = ks * 16;
                uint4 av = tf[ks*32];
                u32 a[4] = {av.x, av.y, av.z, av.w};
                #pragma unroll
                for (int n = 0; n < 8; ++n) {
                    const bf16* bp = sY + (n*8 + g)*SPB + k0 + tig*2;
                    u32 bfr[2] = {*(const u32*)bp, *(const u32*)(bp + 8)};
                    mma16816(accS[n], a, bfr);
                }
            }
        }
        const int r0 = wid*16 + g;
        float z0 = __shfl_sync(0xffffffffu, accL[8][0], lane & ~3);
        float z1 = __shfl_sync(0xffffffffu, accL[8][2], lane & ~3);
        float inv0 = 0.5f / (1024.0f + SCALE_F * z0);
        float inv1 = 0.5f / (1024.0f + SCALE_F * z1);
        #pragma unroll
        for (int n = 0; n < 8; ++n) {
            int col = n*8 + tig*2;
            float2 o0 = make_float2(
                (svs[col]   + SCALE_F*accL[n][0]) * inv0 + accS[n][0],
                (svs[col+1] + SCALE_F*accL[n][1]) * inv0 + accS[n][1]);
            *(float2*)(out + (b*NL + l0 + r0)*HE + h*NE + col) = o0;
            float2 o1 = make_float2(
                (svs[col]   + SCALE_F*accL[n][2]) * inv1 + accS[n][2],
                (svs[col+1] + SCALE_F*accL[n][3]) * inv1 + accS[n][3]);
            *(float2*)(out + (b*NL + l0 + r0 + 8)*HE + h*NE + col) = o1;
        }
        // restage q for tile 1
        if (ti == 0) {
            __syncthreads();
            const int l1 = blockIdx.y*256 + 128;
            #pragma unroll
            for (int it = 0; it < 16; ++it) {
                int idx = it * 256 + t;
                int l = idx >> 5, e2 = idx & 31;
                float2 qv = *(const float2*)(q + base + (l1 + l)*HE + e2*2);
                *(u32*)(sQ + l*SPA + e2*2) = pkbf(qv.x, qv.y);
            }
            __syncthreads();
        }
    }
}

// ===================== launch =====================
extern "C" void kernel_launch(void* const* d_in, const int* in_sizes, int n_in,
                              void* d_out, int out_size) {
    (void)in_sizes; (void)n_in; (void)out_size;
    const float* q   = (const float*)d_in[0];
    const float* k   = (const float*)d_in[1];
    const float* v   = (const float*)d_in[2];
    // d_in[3] = mask (present -> reference applies no masking); unused
    const float* wre = (const float*)d_in[4];
    const float* wim = (const float*)d_in[5];
    float* out = (float*)d_out;

    static int smem_set = 0;
    if (!smem_set) {
        cudaFuncSetAttribute(k_fused, cudaFuncAttributeMaxDynamicSharedMemorySize, FUSED_SMEM);
        smem_set = 1;
    }

    k_tab    <<<32, 256>>>();
    k_front  <<<1536, 256, FRONT_SMEM>>>(wre, wim, k, v, q);
    k_mix_mma<<<704, 128>>>();
    k_fused  <<<dim3(NBH, 4), 256, FUSED_SMEM>>>(q, out);
}

// round 11
// speedup vs baseline: 1.0590x; 1.0106x over previous
#include <cuda_runtime.h>
#include <cuda_bf16.h>

#define NB 16
#define NL 1024
#define NH 8
#define NE 64
#define NM 64
#define NBH (NB*NH)
#define HE 512
#define SCALE_F 3.814697265625e-06f  // 1/(512*512)

typedef unsigned long long u64;
typedef unsigned u32;
typedef __nv_bfloat16 bf16;

// -------- scratch (static device globals) --------
static __device__ float g_Mt[4*NBH*NE*NE];                 // K-split x4 partials of M^T
static __device__ float g_ksp[4*NBH*NE];
static __device__ float g_vsp[4*NBH*NE];
static __device__ __align__(16) bf16 g_X[4*NBH*128*64];    // K-split x4 bf16 partials
static __device__ __align__(16) bf16 g_Mtb[NBH*NE*NE];     // merged M^T bf16: [bh][o][e]
static __device__ float g_ks[NBH*NE];
static __device__ float g_vs[NBH*NE];
static __device__ __align__(16) bf16 g_qb[NBH*NL*NE];      // bf16 q copy: [bh][l][e]
static __device__ __align__(16) bf16 g_Yt[NBH*64*128];     // [bh][o][mr]
static __device__ __align__(16) bf16 g_Tml[128*1024];      // [mr][l]
static __device__ uint4 g_Tfrag[8*8*8*32];                 // [ltile][wid][ks][lane]
static __device__ u32 g_WtR[NH*64*64*64];                  // [h][m][i][o]
static __device__ u32 g_WtI[NH*64*64*64];

// ---------------- warp MMA + async helpers ----------------
__device__ __forceinline__ void mma16816(float* d, const u32* a, const u32* b) {
    asm volatile(
        "mma.sync.aligned.m16n8k16.row.col.f32.bf16.bf16.f32 "
        "{%0,%1,%2,%3}, {%4,%5,%6,%7}, {%8,%9}, {%0,%1,%2,%3};"
        : "+f"(d[0]), "+f"(d[1]), "+f"(d[2]), "+f"(d[3])
        : "r"(a[0]), "r"(a[1]), "r"(a[2]), "r"(a[3]), "r"(b[0]), "r"(b[1]));
}
__device__ __forceinline__ u32 pkbf(float a, float b) {
    __nv_bfloat162 p = __floats2bfloat162_rn(a, b);
    return *(u32*)&p;
}
__device__ __forceinline__ void cpa16(u32 saddr, const void* g) {
    asm volatile("cp.async.cg.shared.global [%0], [%1], 16;" :: "r"(saddr), "l"(g));
}
#define CPA_COMMIT() asm volatile("cp.async.commit_group;" ::: "memory")
#define CPA_WAIT0()  asm volatile("cp.async.wait_group 0;" ::: "memory")

#define SPA 72    // bf16 pitch, K<=64 tiles (144B rows, 16B-aligned)
#define SPB 136   // bf16 pitch, K=128 tiles (272B rows, 16B-aligned)

// ===================== table: Tml via smem cos/sin lookup =====================
__global__ void __launch_bounds__(256) k_tab() {
    __shared__ float2 cs[1024];
    const int t = threadIdx.x;
    #pragma unroll
    for (int r = 0; r < 4; ++r) {
        int j = r*256 + t;
        float s, c;
        sincospif((float)j * (1.0f/512.0f), &s, &c);
        cs[j] = make_float2(c, s);
    }
    __syncthreads();
    #pragma unroll
    for (int r = 0; r < 16; ++r) {
        int idx = r*256 + t;
        int mr = blockIdx.x*4 + (idx >> 10), l = idx & 1023;
        int m = mr >> 1;
        float2 v = cs[(m*l) & 1023];
        g_Tml[mr*1024 + l] = __float2bfloat16((mr & 1) ? v.y : v.x);
    }
}

// ===================== merged front kernel: wt | stats | fdft =====================
#define FRONT_SMEM 33280

__global__ void __launch_bounds__(256, 3) k_front(const float* __restrict__ wre,
                                                  const float* __restrict__ wim,
                                                  const float* __restrict__ kin,
                                                  const float* __restrict__ vin,
                                                  const float* __restrict__ q) {
    extern __shared__ char dyns[];
    const int bx = blockIdx.x;
    const int t = threadIdx.x;

    if (bx < 512) {
        // ---------------- weight transpose ----------------
        float* smr = (float*)dyns;            // [64][65]
        float* smi = smr + 64*65;
        const int hi = bx;
        const int h = hi >> 6, i = hi & 63;
        const float* pr = wre + (size_t)hi * 4096;
        const float* pq = wim + (size_t)hi * 4096;
        #pragma unroll
        for (int it = 0; it < 4; ++it) {
            int idx = it * 256 + t;
            int o = idx >> 4, m4 = idx & 15;
            float4 vr = *(const float4*)(pr + o*64 + m4*4);
            float4 vi = *(const float4*)(pq + o*64 + m4*4);
            smr[o*65 + m4*4+0] = vr.x; smr[o*65 + m4*4+1] = vr.y;
            smr[o*65 + m4*4+2] = vr.z; smr[o*65 + m4*4+3] = vr.w;
            smi[o*65 + m4*4+0] = vi.x; smi[o*65 + m4*4+1] = vi.y;
            smi[o*65 + m4*4+2] = vi.z; smi[o*65 + m4*4+3] = vi.w;
        }
        __syncthreads();
        #pragma unroll
        for (int it = 0; it < 16; ++it) {
            int idx = it * 256 + t;
            int m = idx >> 6, o = idx & 63;
            float wr = smr[o*65 + m], wi = smi[o*65 + m];
            int dst = ((h*64 + m)*64 + i)*64 + o;
            g_WtR[dst] = pkbf(wr, wi);
            g_WtI[dst] = pkbf(wi, -wr);
        }
    } else if (bx < 1024) {
        // ---------------- stats: M^T = v^T k, K-split x4, reg-prefetch ----------------
        bf16* sV = (bf16*)dyns;               // [64][SPA]
        bf16* sK = sV + 64*SPA;
        float* red = (float*)(sK + 64*SPA);   // [256]
        const int z = bx - 512;
        const int bh = z >> 2, ky = z & 3;
        const int b = bh >> 3, h = bh & 7;
        const int wid = t >> 5, lane = t & 31, g = lane >> 2, tig = lane & 3;
        const int ot = wid >> 1, eh = wid & 1;
        const int base = b * NL * HE + h * NE + ky * 256 * HE;
        const int s0 = t >> 6, o0 = t & 63;
        float pk[16], pv[16];
        #pragma unroll
        for (int it = 0; it < 16; ++it) {
            int off = base + (s0 + it*4)*HE + o0;
            pk[it] = kin[off];
            pv[it] = vin[off];
        }
        float ka = 0.f, va = 0.f;
        float acc[4][4] = {};
        for (int c = 0; c < 4; ++c) {
            __syncthreads();
            #pragma unroll
            for (int it = 0; it < 16; ++it) {
                int s = s0 + it*4;
                sK[o0*SPA + s] = __float2bfloat16(pk[it]);
                sV[o0*SPA + s] = __float2bfloat16(pv[it]);
                ka += pk[it]; va += pv[it];
            }
            if (c < 3) {
                #pragma unroll
                for (int it = 0; it < 16; ++it) {
                    int off = base + ((c+1)*64 + s0 + it*4)*HE + o0;
                    pk[it] = kin[off];
                    pv[it] = vin[off];
                }
            }
            __syncthreads();
            #pragma unroll
            for (int ks = 0; ks < 4; ++ks) {
                const int k0 = ks * 16;
                u32 a[4];
                const bf16* ap = sV + (ot*16 + g)*SPA + k0 + tig*2;
                a[0] = *(const u32*)ap;
                a[1] = *(const u32*)(ap + 8*SPA);
                a[2] = *(const u32*)(ap + 8);
                a[3] = *(const u32*)(ap + 8*SPA + 8);
                #pragma unroll
                for (int n = 0; n < 4; ++n) {
                    const bf16* bp = sK + (eh*32 + n*8 + g)*SPA + k0 + tig*2;
                    u32 bfr[2] = {*(const u32*)bp, *(const u32*)(bp + 8)};
                    mma16816(acc[n], a, bfr);
                }
            }
        }
        float* Mo = g_Mt + (bh*4 + ky) * 4096;
        const int oo0 = ot*16 + g;
        #pragma unroll
        for (int n = 0; n < 4; ++n) {
            int col = eh*32 + n*8 + tig*2;
            *(float2*)(Mo + oo0*64 + col)     = make_float2(acc[n][0], acc[n][1]);
            *(float2*)(Mo + (oo0+8)*64 + col) = make_float2(acc[n][2], acc[n][3]);
        }
        red[t] = ka; __syncthreads();
        if (t < 64) g_ksp[(bh*4+ky)*64 + t] = red[t] + red[t+64] + red[t+128] + red[t+192];
        __syncthreads();
        red[t] = va; __syncthreads();
        if (t < 64) g_vsp[(bh*4+ky)*64 + t] = red[t] + red[t+64] + red[t+128] + red[t+192];
    } else {
        // ---------------- forward DFT, K-split x4, reg-prefetch; also emits g_qb ----------------
        bf16* sA = (bf16*)dyns;               // [128][SPA]
        bf16* sB = sA + 128*SPA;              // [64][SPA]
        const int z = bx - 1024;
        const int bh = z >> 2, ky = z & 3;
        const int b = bh >> 3, h = bh & 7;
        const int wid = t >> 5, lane = t & 31, g = lane >> 2, tig = lane & 3;
        const int base = b * NL * HE + h * NE;
        const int l00 = t >> 6, e0 = t & 63;
        float pq[16];
        #pragma unroll
        for (int it = 0; it < 16; ++it)
            pq[it] = q[base + (ky*256 + l00 + it*4)*HE + e0];
        float acc[8][4] = {};
        bf16* qbb = g_qb + bh*(NL*NE);
        for (int c = 0; c < 4; ++c) {
            const int cc = ky*4 + c;
            __syncthreads();
            #pragma unroll
            for (int it = 0; it < 16; ++it) {
                int idx = it * 256 + t;
                int row = idx >> 5, w = idx & 31;
                ((u32*)(sA + row*SPA))[w] = ((const u32*)(g_Tml + row*1024 + cc*64))[w];
            }
            #pragma unroll
            for (int it = 0; it < 16; ++it) {
                bf16 bv = __float2bfloat16(pq[it]);
                sB[e0*SPA + (l00 + it*4)] = bv;
                qbb[(ky*256 + c*64 + l00 + it*4)*64 + e0] = bv;
            }
            if (c < 3) {
                #pragma unroll
                for (int it = 0; it < 16; ++it)
                    pq[it] = q[base + (ky*256 + (c+1)*64 + l00 + it*4)*HE + e0];
            }
            __syncthreads();
            #pragma unroll
            for (int ks = 0; ks < 4; ++ks) {
                const int k0 = ks * 16;
                u32 a[4];
                const bf16* ap = sA + (wid*16 + g)*SPA + k0 + tig*2;
                a[0] = *(const u32*)ap;
                a[1] = *(const u32*)(ap + 8*SPA);
                a[2] = *(const u32*)(ap + 8);
                a[3] = *(const u32*)(ap + 8*SPA + 8);
                #pragma unroll
                for (int n = 0; n < 8; ++n) {
                    const bf16* bp = sB + (n*8 + g)*SPA + k0 + tig*2;
                    u32 bfr[2] = {*(const u32*)bp, *(const u32*)(bp + 8)};
                    mma16816(acc[n], a, bfr);
                }
            }
        }
        bf16* Xb = g_X + (bh*4 + ky) * 8192;
        const int m0 = wid*16 + g;
        #pragma unroll
        for (int n = 0; n < 8; ++n) {
            int col = n*8 + tig*2;
            *(u32*)(Xb + m0*64 + col)     = pkbf(acc[n][0], acc[n][1]);
            *(u32*)(Xb + (m0+8)*64 + col) = pkbf(acc[n][2], acc[n][3]);
        }
    }
}

// ===================== kernel C: mix | Mt merge | Tfrag gen =====================
__global__ void __launch_bounds__(128) k_mix_mma() {
    __shared__ bf16 sA[16][SPB];
    __shared__ bf16 sBr[64][SPB];
    __shared__ bf16 sBi[64][SPB];
    const int bx = blockIdx.x;
    const int t = threadIdx.x;
    if (bx >= 640) {
        #pragma unroll
        for (int r = 0; r < 2; ++r) {
            int idx = (bx - 640)*256 + r*128 + t;
            int lt = idx >> 11, wid = (idx >> 8) & 7, ks = (idx >> 5) & 7, lane = idx & 31;
            int g = lane >> 2, tig = lane & 3;
            int rr = lt*128 + wid*16 + g;
            int m = ks*8 + tig;
            float s0,c0,s1,c1,s2,c2,s3,c3;
            sincospif((float)((m*rr)        & 1023) * (1.0f/512.0f), &s0, &c0);
            sincospif((float)((m*(rr+8))    & 1023) * (1.0f/512.0f), &s1, &c1);
            sincospif((float)(((m+4)*rr)    & 1023) * (1.0f/512.0f), &s2, &c2);
            sincospif((float)(((m+4)*(rr+8))& 1023) * (1.0f/512.0f), &s3, &c3);
            uint4 v;
            v.x = pkbf(c0, s0); v.y = pkbf(c1, s1); v.z = pkbf(c2, s2); v.w = pkbf(c3, s3);
            g_Tfrag[idx] = v;
        }
        return;
    }
    if (bx >= 512) {
        const int bh = bx - 512;
        const float* Mp = g_Mt + bh*4*4096;
        for (int idx = t; idx < 4096; idx += 128) {
            float s = Mp[idx] + Mp[4096 + idx] + Mp[8192 + idx] + Mp[12288 + idx];
            g_Mtb[bh*4096 + idx] = __float2bfloat16(s);
        }
        if (t < 64) {
            const float* kp = g_ksp + bh*4*64;
            const float* vp = g_vsp + bh*4*64;
            g_ks[bh*64 + t] = kp[t] + kp[64+t] + kp[128+t] + kp[192+t];
            g_vs[bh*64 + t] = vp[t] + vp[64+t] + vp[128+t] + vp[192+t];
        }
        return;
    }
    const int h = bx >> 6, m = bx & 63;
    const int wid = t >> 5, lane = t & 31, g = lane >> 2, tig = lane & 3;
    #pragma unroll
    for (int it = 0; it < 8; ++it) {
        int idx = it * 128 + t;
        int bb = idx >> 6, i = idx & 63;
        const bf16* X0 = g_X + ((bb*8 + h)*4)*8192 + (2*m)*64;
        float xc = 0.f, xs = 0.f;
        #pragma unroll
        for (int ky = 0; ky < 4; ++ky) {
            xc += __bfloat162float(X0[ky*8192 + i]);
            xs += __bfloat162float(X0[ky*8192 + 64 + i]);
        }
        *(u32*)&sA[bb][2*i] = pkbf(xc, xs);
    }
    const u32* WR = g_WtR + (h*64 + m)*4096;
    const u32* WI = g_WtI + (h*64 + m)*4096;
    #pragma unroll
    for (int it = 0; it < 32; ++it) {
        int idx = it * 128 + t;
        int i = idx >> 6, o = idx & 63;
        *(u32*)&sBr[o][2*i] = WR[i*64 + o];
        *(u32*)&sBi[o][2*i] = WI[i*64 + o];
    }
    __syncthreads();
    float acc[2][2][4] = {};
    #pragma unroll
    for (int ks = 0; ks < 8; ++ks) {
        const int k0 = ks * 16;
        u32 a[4];
        const bf16* ap = &sA[g][k0 + tig*2];
        a[0] = *(const u32*)ap;
        a[1] = *(const u32*)(ap + 8*SPB);
        a[2] = *(const u32*)(ap + 8);
        a[3] = *(const u32*)(ap + 8*SPB + 8);
        #pragma unroll
        for (int n = 0; n < 2; ++n) {
            int o = wid*16 + n*8 + g;
            const bf16* brp = &sBr[o][k0 + tig*2];
            u32 br[2] = {*(const u32*)brp, *(const u32*)(brp + 8)};
            mma16816(acc[0][n], a, br);
            const bf16* bip = &sBi[o][k0 + tig*2];
            u32 bi2[2] = {*(const u32*)bip, *(const u32*)(bip + 8)};
            mma16816(acc[1][n], a, bi2);
        }
    }
    const float f = (m == 0 ? 1.0f : 2.0f) * (1.0f / 2048.0f);
    u32* Yt32 = (u32*)g_Yt;
    #pragma unroll
    for (int n = 0; n < 2; ++n)
        #pragma unroll
        for (int cc = 0; cc < 2; ++cc) {
            int o = wid*16 + n*8 + tig*2 + cc;
            Yt32[((g*8 + h)*64 + o)*64 + m]     = pkbf(f*acc[0][n][cc],   -f*acc[1][n][cc]);
            Yt32[(((g+8)*8 + h)*64 + o)*64 + m] = pkbf(f*acc[0][n][cc+2], -f*acc[1][n][cc+2]);
        }
}

// ===================== fused D: single wave, 4 tiles/block, cp.async double-buffered =====================
#define FQ0_OFF 0
#define FQ1_OFF 18432
#define FM_OFF  36864
#define FY_OFF  47232
#define FV_OFF  64640
#define FUSED_SMEM 64896

__global__ void __launch_bounds__(256, 2) k_fused(float* __restrict__ out) {
    extern __shared__ char dyns[];
    bf16*  sQb[2] = {(bf16*)(dyns + FQ0_OFF), (bf16*)(dyns + FQ1_OFF)};  // [128][SPA]
    bf16*  sMt = (bf16*)(dyns + FM_OFF);    // [72][SPA]
    bf16*  sY  = (bf16*)(dyns + FY_OFF);    // [64][SPB]
    float* svs = (float*)(dyns + FV_OFF);
    const int bh = blockIdx.x;
    const int b = bh >> 3, h = bh & 7;
    const int t = threadIdx.x;
    const int wid = t >> 5, lane = t & 31, g = lane >> 2, tig = lane & 3;
    const bf16* qbb = g_qb + bh*(NL*NE);

    // async stage: sMt rows 0-63 (64 rows x 8 x16B)
    #pragma unroll
    for (int r = 0; r < 2; ++r) {
        int idx = r*256 + t;
        int row = idx >> 3, w = idx & 7;
        u32 sa = (u32)__cvta_generic_to_shared(sMt + row*SPA) + w*16;
        cpa16(sa, (const char*)(g_Mtb + bh*4096 + row*64) + w*16);
    }
    // async stage: sY (64 rows x 16 x16B)
    #pragma unroll
    for (int r = 0; r < 4; ++r) {
        int idx = r*256 + t;
        int row = idx >> 4, w = idx & 15;
        u32 sa = (u32)__cvta_generic_to_shared(sY + row*SPB) + w*16;
        cpa16(sa, (const char*)(g_Yt + bh*8192 + row*128) + w*16);
    }
    // async stage: sQ[0] tile 0 (128 rows x 8 x16B)
    {
        const int l0 = blockIdx.y * 512;
        #pragma unroll
        for (int r = 0; r < 4; ++r) {
            int idx = r*256 + t;
            int row = idx >> 3, w = idx & 7;
            u32 sa = (u32)__cvta_generic_to_shared(sQb[0] + row*SPA) + w*16;
            cpa16(sa, (const char*)(qbb + (l0 + row)*64) + w*16);
        }
    }
    // scalar rows: ksum (row 64), zero rows, svs
    if (t < 64) {
        sMt[64*SPA + t] = __float2bfloat16(g_ks[bh*64 + t]);
        svs[t] = g_vs[bh*64 + t];
    }
    for (int idx = t; idx < 7*SPA; idx += 256)
        sMt[65*SPA + idx] = __float2bfloat16(0.f);
    CPA_COMMIT();
    CPA_WAIT0();
    __syncthreads();

    int p = 0;
    for (int ti = 0; ti < 4; ++ti) {
        const int lt = blockIdx.y*4 + ti;
        const int l0 = lt * 128;
        // prefetch next tile's q into the other buffer
        if (ti < 3) {
            const int l1 = blockIdx.y*512 + (ti+1)*128;
            #pragma unroll
            for (int r = 0; r < 4; ++r) {
                int idx = r*256 + t;
                int row = idx >> 3, w = idx & 7;
                u32 sa = (u32)__cvta_generic_to_shared(sQb[p^1] + row*SPA) + w*16;
                cpa16(sa, (const char*)(qbb + (l1 + row)*64) + w*16);
            }
            CPA_COMMIT();
        }
        const bf16* sQ = sQb[p];
        float accL[9][4] = {};
        float accS[8][4] = {};
        // local: K=64
        #pragma unroll
        for (int ks = 0; ks < 4; ++ks) {
            const int k0 = ks * 16;
            u32 a[4];
            const bf16* ap = sQ + (wid*16 + g)*SPA + k0 + tig*2;
            a[0] = *(const u32*)ap;
            a[1] = *(const u32*)(ap + 8*SPA);
            a[2] = *(const u32*)(ap + 8);
            a[3] = *(const u32*)(ap + 8*SPA + 8);
            #pragma unroll
            for (int n = 0; n < 9; ++n) {
                const bf16* bp = sMt + (n*8 + g)*SPA + k0 + tig*2;
                u32 bfr[2] = {*(const u32*)bp, *(const u32*)(bp + 8)};
                mma16816(accL[n], a, bfr);
            }
        }
        // spec: K=128, A-frags from g_Tfrag with software prefetch
        {
            const uint4* tf = g_Tfrag + ((lt*8 + wid)*8)*32 + lane;
            uint4 av = tf[0];
            #pragma unroll
            for (int ks = 0; ks < 8; ++ks) {
                const int k0 = ks * 16;
                uint4 nv = (ks < 7) ? tf[(ks+1)*32] : av;
                u32 a[4] = {av.x, av.y, av.z, av.w};
                #pragma unroll
                for (int n = 0; n < 8; ++n) {
                    const bf16* bp = sY + (n*8 + g)*SPB + k0 + tig*2;
                    u32 bfr[2] = {*(const u32*)bp, *(const u32*)(bp + 8)};
                    mma16816(accS[n], a, bfr);
                }
                av = nv;
            }
        }
        const int r0 = wid*16 + g;
        float z0 = __shfl_sync(0xffffffffu, accL[8][0], lane & ~3);
        float z1 = __shfl_sync(0xffffffffu, accL[8][2], lane & ~3);
        float inv0 = 0.5f / (1024.0f + SCALE_F * z0);
        float inv1 = 0.5f / (1024.0f + SCALE_F * z1);
        #pragma unroll
        for (int n = 0; n < 8; ++n) {
            int col = n*8 + tig*2;
            float2 o0 = make_float2(
                (svs[col]   + SCALE_F*accL[n][0]) * inv0 + accS[n][0],
                (svs[col+1] + SCALE_F*accL[n][1]) * inv0 + accS[n][1]);
            *(float2*)(out + (b*NL + l0 + r0)*HE + h*NE + col) = o0;
            float2 o1 = make_float2(
                (svs[col]   + SCALE_F*accL[n][2]) * inv1 + accS[n][2],
                (svs[col+1] + SCALE_F*accL[n][3]) * inv1 + accS[n][3]);
            *(float2*)(out + (b*NL + l0 + r0 + 8)*HE + h*NE + col) = o1;
        }
        if (ti < 3) {
            CPA_WAIT0();
            __syncthreads();
            p ^= 1;
        }
    }
}

// ===================== launch =====================
extern "C" void kernel_launch(void* const* d_in, const int* in_sizes, int n_in,
                              void* d_out, int out_size) {
    (void)in_sizes; (void)n_in; (void)out_size;
    const float* q   = (const float*)d_in[0];
    const float* k   = (const float*)d_in[1];
    const float* v   = (const float*)d_in[2];
    // d_in[3] = mask (present -> reference applies no masking); unused
    const float* wre = (const float*)d_in[4];
    const float* wim = (const float*)d_in[5];
    float* out = (float*)d_out;

    static int smem_set = 0;
    if (!smem_set) {
        cudaFuncSetAttribute(k_fused, cudaFuncAttributeMaxDynamicSharedMemorySize, FUSED_SMEM);
        smem_set = 1;
    }

    k_tab    <<<32, 256>>>();
    k_front  <<<1536, 256, FRONT_SMEM>>>(wre, wim, k, v, q);
    k_mix_mma<<<704, 128>>>();
    k_fused  <<<dim3(NBH, 2), 256, FUSED_SMEM>>>(out);
}

// round 13
// speedup vs baseline: 1.0730x; 1.0133x over previous
#include <cuda_runtime.h>
#include <cuda_bf16.h>

#define NB 16
#define NL 1024
#define NH 8
#define NE 64
#define NM 64
#define NBH (NB*NH)
#define HE 512
#define SCALE_F 3.814697265625e-06f  // 1/(512*512)

typedef unsigned long long u64;
typedef unsigned u32;
typedef __nv_bfloat16 bf16;

// -------- scratch (static device globals) --------
static __device__ float g_Mt[4*NBH*NE*NE];
static __device__ float g_ksp[4*NBH*NE];
static __device__ float g_vsp[4*NBH*NE];
static __device__ __align__(16) bf16 g_X[4*NBH*128*64];
static __device__ __align__(16) bf16 g_Mtb[NBH*NE*NE];
static __device__ float g_ks[NBH*NE];
static __device__ float g_vs[NBH*NE];
static __device__ __align__(16) bf16 g_qb[NBH*NL*NE];
static __device__ __align__(16) bf16 g_Yt[NBH*64*128];
static __device__ __align__(16) bf16 g_Tml[128*1024];
static __device__ uint4 g_Tfrag[8*8*8*32];
static __device__ u32 g_WtR[NH*64*64*64];
static __device__ u32 g_WtI[NH*64*64*64];

// -------- global barrier state (count returns to 0 each barrier; sense is
// read at kernel start before any block can flip it, so replay-safe) --------
static __device__ unsigned g_cnt = 0;
static __device__ volatile unsigned g_sns = 0;

// ---------------- helpers ----------------
__device__ __forceinline__ void mma16816(float* d, const u32* a, const u32* b) {
    asm volatile(
        "mma.sync.aligned.m16n8k16.row.col.f32.bf16.bf16.f32 "
        "{%0,%1,%2,%3}, {%4,%5,%6,%7}, {%8,%9}, {%0,%1,%2,%3};"
        : "+f"(d[0]), "+f"(d[1]), "+f"(d[2]), "+f"(d[3])
        : "r"(a[0]), "r"(a[1]), "r"(a[2]), "r"(a[3]), "r"(b[0]), "r"(b[1]));
}
__device__ __forceinline__ u32 pkbf(float a, float b) {
    __nv_bfloat162 p = __floats2bfloat162_rn(a, b);
    return *(u32*)&p;
}
__device__ __forceinline__ void cpa16(u32 saddr, const void* g) {
    asm volatile("cp.async.cg.shared.global [%0], [%1], 16;" :: "r"(saddr), "l"(g));
}
#define CPA_COMMIT() asm volatile("cp.async.commit_group;" ::: "memory")
#define CPA_WAIT0()  asm volatile("cp.async.wait_group 0;" ::: "memory")

#define SPA 72
#define SPB 136

#define FQ0_OFF 0
#define FQ1_OFF 18432
#define FM_OFF  36864
#define FY_OFF  47232
#define FV_OFF  64640
#define MEGA_SMEM 64896

// ===================== unit: weight transpose =====================
__device__ void dev_wt(int u, char* dyns, const float* __restrict__ wre,
                       const float* __restrict__ wim, int t) {
    float* smr = (float*)dyns;            // [64][65]
    float* smi = smr + 64*65;
    const int h = u >> 6, i = u & 63;
    const float* pr = wre + (size_t)u * 4096;
    const float* pq = wim + (size_t)u * 4096;
    #pragma unroll
    for (int it = 0; it < 4; ++it) {
        int idx = it * 256 + t;
        int o = idx >> 4, m4 = idx & 15;
        float4 vr = *(const float4*)(pr + o*64 + m4*4);
        float4 vi = *(const float4*)(pq + o*64 + m4*4);
        smr[o*65 + m4*4+0] = vr.x; smr[o*65 + m4*4+1] = vr.y;
        smr[o*65 + m4*4+2] = vr.z; smr[o*65 + m4*4+3] = vr.w;
        smi[o*65 + m4*4+0] = vi.x; smi[o*65 + m4*4+1] = vi.y;
        smi[o*65 + m4*4+2] = vi.z; smi[o*65 + m4*4+3] = vi.w;
    }
    __syncthreads();
    #pragma unroll
    for (int it = 0; it < 16; ++it) {
        int idx = it * 256 + t;
        int m = idx >> 6, o = idx & 63;
        float wr = smr[o*65 + m], wi = smi[o*65 + m];
        int dst = ((h*64 + m)*64 + i)*64 + o;
        g_WtR[dst] = pkbf(wr, wi);
        g_WtI[dst] = pkbf(wi, -wr);
    }
}

// ===================== unit: Tml gen (32 units) =====================
__device__ void dev_tml(int u, const u32* csb, int t) {
    #pragma unroll
    for (int r = 0; r < 16; ++r) {
        int idx = r*256 + t;
        int mr = u*4 + (idx >> 10), l = idx & 1023;
        int m = mr >> 1;
        u32 v = csb[(m*l) & 1023];
        g_Tml[mr*1024 + l] = ((const bf16*)&v)[mr & 1];
    }
}

// ===================== unit: Tfrag gen (64 units) =====================
__device__ void dev_tfrag(int u, const u32* csb, int t) {
    int idx = u*256 + t;
    int lt = idx >> 11, wid = (idx >> 8) & 7, ks = (idx >> 5) & 7, lane = idx & 31;
    int g = lane >> 2, tig = lane & 3;
    int rr = lt*128 + wid*16 + g;
    int m = ks*8 + tig;
    uint4 v;
    v.x = csb[(m*rr) & 1023];
    v.y = csb[(m*(rr+8)) & 1023];
    v.z = csb[((m+4)*rr) & 1023];
    v.w = csb[((m+4)*(rr+8)) & 1023];
    g_Tfrag[idx] = v;
}

// ===================== unit: stats (512 units) =====================
__device__ void dev_stats(int u, char* dyns, const float* __restrict__ kin,
                          const float* __restrict__ vin, int t) {
    bf16* sV = (bf16*)dyns;               // [64][SPA]
    bf16* sK = sV + 64*SPA;
    float* red = (float*)(sK + 64*SPA);   // [256]
    const int bh = u >> 2, ky = u & 3;
    const int b = bh >> 3, h = bh & 7;
    const int wid = t >> 5, lane = t & 31, g = lane >> 2, tig = lane & 3;
    const int ot = wid >> 1, eh = wid & 1;
    const int base = b * NL * HE + h * NE + ky * 256 * HE;
    const int s0 = t >> 6, o0 = t & 63;
    float pk[16], pv[16];
    #pragma unroll
    for (int it = 0; it < 16; ++it) {
        int off = base + (s0 + it*4)*HE + o0;
        pk[it] = kin[off];
        pv[it] = vin[off];
    }
    float ka = 0.f, va = 0.f;
    float acc[4][4] = {};
    for (int c = 0; c < 4; ++c) {
        __syncthreads();
        #pragma unroll
        for (int it = 0; it < 16; ++it) {
            int s = s0 + it*4;
            sK[o0*SPA + s] = __float2bfloat16(pk[it]);
            sV[o0*SPA + s] = __float2bfloat16(pv[it]);
            ka += pk[it]; va += pv[it];
        }
        if (c < 3) {
            #pragma unroll
            for (int it = 0; it < 16; ++it) {
                int off = base + ((c+1)*64 + s0 + it*4)*HE + o0;
                pk[it] = kin[off];
                pv[it] = vin[off];
            }
        }
        __syncthreads();
        #pragma unroll
        for (int ks = 0; ks < 4; ++ks) {
            const int k0 = ks * 16;
            u32 a[4];
            const bf16* ap = sV + (ot*16 + g)*SPA + k0 + tig*2;
            a[0] = *(const u32*)ap;
            a[1] = *(const u32*)(ap + 8*SPA);
            a[2] = *(const u32*)(ap + 8);
            a[3] = *(const u32*)(ap + 8*SPA + 8);
            #pragma unroll
            for (int n = 0; n < 4; ++n) {
                const bf16* bp = sK + (eh*32 + n*8 + g)*SPA + k0 + tig*2;
                u32 bfr[2] = {*(const u32*)bp, *(const u32*)(bp + 8)};
                mma16816(acc[n], a, bfr);
            }
        }
    }
    float* Mo = g_Mt + (bh*4 + ky) * 4096;
    const int oo0 = ot*16 + g;
    #pragma unroll
    for (int n = 0; n < 4; ++n) {
        int col = eh*32 + n*8 + tig*2;
        *(float2*)(Mo + oo0*64 + col)     = make_float2(acc[n][0], acc[n][1]);
        *(float2*)(Mo + (oo0+8)*64 + col) = make_float2(acc[n][2], acc[n][3]);
    }
    __syncthreads();
    red[t] = ka; __syncthreads();
    if (t < 64) g_ksp[(bh*4+ky)*64 + t] = red[t] + red[t+64] + red[t+128] + red[t+192];
    __syncthreads();
    red[t] = va; __syncthreads();
    if (t < 64) g_vsp[(bh*4+ky)*64 + t] = red[t] + red[t+64] + red[t+128] + red[t+192];
}

// ===================== unit: forward DFT (512 units) =====================
__device__ void dev_fdft(int u, char* dyns, const float* __restrict__ q, int t) {
    bf16* sA = (bf16*)dyns;               // [128][SPA]
    bf16* sB = sA + 128*SPA;              // [64][SPA]
    const int bh = u >> 2, ky = u & 3;
    const int b = bh >> 3, h = bh & 7;
    const int wid = t >> 5, lane = t & 31, g = lane >> 2, tig = lane & 3;
    const int base = b * NL * HE + h * NE;
    const int l00 = t >> 6, e0 = t & 63;
    float pq[16];
    #pragma unroll
    for (int it = 0; it < 16; ++it)
        pq[it] = q[base + (ky*256 + l00 + it*4)*HE + e0];
    float acc[8][4] = {};
    bf16* qbb = g_qb + bh*(NL*NE);
    for (int c = 0; c < 4; ++c) {
        const int cc = ky*4 + c;
        __syncthreads();
        #pragma unroll
        for (int it = 0; it < 16; ++it) {
            int idx = it * 256 + t;
            int row = idx >> 5, w = idx & 31;
            ((u32*)(sA + row*SPA))[w] = ((const u32*)(g_Tml + row*1024 + cc*64))[w];
        }
        #pragma unroll
        for (int it = 0; it < 16; ++it) {
            bf16 bv = __float2bfloat16(pq[it]);
            sB[e0*SPA + (l00 + it*4)] = bv;
            qbb[(ky*256 + c*64 + l00 + it*4)*64 + e0] = bv;
        }
        if (c < 3) {
            #pragma unroll
            for (int it = 0; it < 16; ++it)
                pq[it] = q[base + (ky*256 + (c+1)*64 + l00 + it*4)*HE + e0];
        }
        __syncthreads();
        #pragma unroll
        for (int ks = 0; ks < 4; ++ks) {
            const int k0 = ks * 16;
            u32 a[4];
            const bf16* ap = sA + (wid*16 + g)*SPA + k0 + tig*2;
            a[0] = *(const u32*)ap;
            a[1] = *(const u32*)(ap + 8*SPA);
            a[2] = *(const u32*)(ap + 8);
            a[3] = *(const u32*)(ap + 8*SPA + 8);
            #pragma unroll
            for (int n = 0; n < 8; ++n) {
                const bf16* bp = sB + (n*8 + g)*SPA + k0 + tig*2;
                u32 bfr[2] = {*(const u32*)bp, *(const u32*)(bp + 8)};
                mma16816(acc[n], a, bfr);
            }
        }
    }
    bf16* Xb = g_X + (bh*4 + ky) * 8192;
    const int m0 = wid*16 + g;
    #pragma unroll
    for (int n = 0; n < 8; ++n) {
        int col = n*8 + tig*2;
        *(u32*)(Xb + m0*64 + col)     = pkbf(acc[n][0], acc[n][1]);
        *(u32*)(Xb + (m0+8)*64 + col) = pkbf(acc[n][2], acc[n][3]);
    }
}

// ===================== unit: mix (512 units) =====================
__device__ void dev_mix(int u, char* dyns, int t) {
    bf16* sA  = (bf16*)dyns;              // [16][SPB]
    bf16* sBr = sA + 16*SPB;              // [64][SPB]
    bf16* sBi = sBr + 64*SPB;             // [64][SPB]
    const int h = u >> 6, m = u & 63;
    const int wid = t >> 5, lane = t & 31, g = lane >> 2, tig = lane & 3;
    #pragma unroll
    for (int it = 0; it < 4; ++it) {
        int idx = it * 256 + t;
        int bb = idx >> 6, i = idx & 63;
        const bf16* X0 = g_X + ((bb*8 + h)*4)*8192 + (2*m)*64;
        float xc = 0.f, xs = 0.f;
        #pragma unroll
        for (int ky = 0; ky < 4; ++ky) {
            xc += __bfloat162float(X0[ky*8192 + i]);
            xs += __bfloat162float(X0[ky*8192 + 64 + i]);
        }
        *(u32*)&sA[bb*SPB + 2*i] = pkbf(xc, xs);
    }
    const u32* WR = g_WtR + (h*64 + m)*4096;
    const u32* WI = g_WtI + (h*64 + m)*4096;
    #pragma unroll
    for (int it = 0; it < 16; ++it) {
        int idx = it * 256 + t;
        int i = idx >> 6, o = idx & 63;
        *(u32*)&sBr[o*SPB + 2*i] = WR[i*64 + o];
        *(u32*)&sBi[o*SPB + 2*i] = WI[i*64 + o];
    }
    __syncthreads();
    if (t < 128) {
        float acc[2][2][4] = {};
        #pragma unroll
        for (int ks = 0; ks < 8; ++ks) {
            const int k0 = ks * 16;
            u32 a[4];
            const bf16* ap = &sA[g*SPB + k0 + tig*2];
            a[0] = *(const u32*)ap;
            a[1] = *(const u32*)(ap + 8*SPB);
            a[2] = *(const u32*)(ap + 8);
            a[3] = *(const u32*)(ap + 8*SPB + 8);
            #pragma unroll
            for (int n = 0; n < 2; ++n) {
                int o = wid*16 + n*8 + g;
                const bf16* brp = &sBr[o*SPB + k0 + tig*2];
                u32 br[2] = {*(const u32*)brp, *(const u32*)(brp + 8)};
                mma16816(acc[0][n], a, br);
                const bf16* bip = &sBi[o*SPB + k0 + tig*2];
                u32 bi2[2] = {*(const u32*)bip, *(const u32*)(bip + 8)};
                mma16816(acc[1][n], a, bi2);
            }
        }
        const float f = (m == 0 ? 1.0f : 2.0f) * (1.0f / 2048.0f);
        u32* Yt32 = (u32*)g_Yt;
        #pragma unroll
        for (int n = 0; n < 2; ++n)
            #pragma unroll
            for (int cc = 0; cc < 2; ++cc) {
                int o = wid*16 + n*8 + tig*2 + cc;
                Yt32[((g*8 + h)*64 + o)*64 + m]     = pkbf(f*acc[0][n][cc],   -f*acc[1][n][cc]);
                Yt32[(((g+8)*8 + h)*64 + o)*64 + m] = pkbf(f*acc[0][n][cc+2], -f*acc[1][n][cc+2]);
            }
    }
}

// ===================== unit: Mt/ksum/vsum merge (128 units) =====================
__device__ void dev_merge(int u, int t) {
    const float* Mp = g_Mt + u*4*4096;
    for (int idx = t; idx < 4096; idx += 256) {
        float s = Mp[idx] + Mp[4096 + idx] + Mp[8192 + idx] + Mp[12288 + idx];
        g_Mtb[u*4096 + idx] = __float2bfloat16(s);
    }
    if (t < 64) {
        const float* kp = g_ksp + u*4*64;
        const float* vp = g_vsp + u*4*64;
        g_ks[u*64 + t] = kp[t] + kp[64+t] + kp[128+t] + kp[192+t];
        g_vs[u*64 + t] = vp[t] + vp[64+t] + vp[128+t] + vp[192+t];
    }
}

// ===================== unit: fused (256 units) =====================
__device__ void dev_fused(int u, char* dyns, float* __restrict__ out, int t) {
    bf16*  sQ0 = (bf16*)(dyns + FQ0_OFF);
    bf16*  sQ1 = (bf16*)(dyns + FQ1_OFF);
    bf16*  sMt = (bf16*)(dyns + FM_OFF);
    bf16*  sY  = (bf16*)(dyns + FY_OFF);
    float* svs = (float*)(dyns + FV_OFF);
    const int bh = u & 127;
    const int half = u >> 7;
    const int b = bh >> 3, h = bh & 7;
    const int wid = t >> 5, lane = t & 31, g = lane >> 2, tig = lane & 3;
    const bf16* qbb = g_qb + bh*(NL*NE);

    #pragma unroll
    for (int r = 0; r < 2; ++r) {
        int idx = r*256 + t;
        int row = idx >> 3, w = idx & 7;
        u32 sa = (u32)__cvta_generic_to_shared(sMt + row*SPA) + w*16;
        cpa16(sa, (const char*)(g_Mtb + bh*4096 + row*64) + w*16);
    }
    #pragma unroll
    for (int r = 0; r < 4; ++r) {
        int idx = r*256 + t;
        int row = idx >> 4, w = idx & 15;
        u32 sa = (u32)__cvta_generic_to_shared(sY + row*SPB) + w*16;
        cpa16(sa, (const char*)(g_Yt + bh*8192 + row*128) + w*16);
    }
    {
        const int l0 = half * 512;
        #pragma unroll
        for (int r = 0; r < 4; ++r) {
            int idx = r*256 + t;
            int row = idx >> 3, w = idx & 7;
            u32 sa = (u32)__cvta_generic_to_shared(sQ0 + row*SPA) + w*16;
            cpa16(sa, (const char*)(qbb + (l0 + row)*64) + w*16);
        }
    }
    if (t < 64) {
        sMt[64*SPA + t] = __float2bfloat16(g_ks[bh*64 + t]);
        svs[t] = g_vs[bh*64 + t];
    }
    for (int idx = t; idx < 7*SPA; idx += 256)
        sMt[65*SPA + idx] = __float2bfloat16(0.f);
    CPA_COMMIT();
    CPA_WAIT0();
    __syncthreads();

    bf16* sQb[2] = {sQ0, sQ1};
    int p = 0;
    for (int ti = 0; ti < 4; ++ti) {
        const int lt = half*4 + ti;
        const int l0 = lt * 128;
        if (ti < 3) {
            const int l1 = half*512 + (ti+1)*128;
            #pragma unroll
            for (int r = 0; r < 4; ++r) {
                int idx = r*256 + t;
                int row = idx >> 3, w = idx & 7;
                u32 sa = (u32)__cvta_generic_to_shared(sQb[p^1] + row*SPA) + w*16;
                cpa16(sa, (const char*)(qbb + (l1 + row)*64) + w*16);
            }
            CPA_COMMIT();
        }
        const bf16* sQ = sQb[p];
        float accL[9][4] = {};
        float accS[8][4] = {};
        #pragma unroll
        for (int ks = 0; ks < 4; ++ks) {
            const int k0 = ks * 16;
            u32 a[4];
            const bf16* ap = sQ + (wid*16 + g)*SPA + k0 + tig*2;
            a[0] = *(const u32*)ap;
            a[1] = *(const u32*)(ap + 8*SPA);
            a[2] = *(const u32*)(ap + 8);
            a[3] = *(const u32*)(ap + 8*SPA + 8);
            #pragma unroll
            for (int n = 0; n < 9; ++n) {
                const bf16* bp = sMt + (n*8 + g)*SPA + k0 + tig*2;
                u32 bfr[2] = {*(const u32*)bp, *(const u32*)(bp + 8)};
                mma16816(accL[n], a, bfr);
            }
        }
        {
            const uint4* tf = g_Tfrag + ((lt*8 + wid)*8)*32 + lane;
            uint4 av = tf[0];
            #pragma unroll
            for (int ks = 0; ks < 8; ++ks) {
                const int k0 = ks * 16;
                uint4 nv = (ks < 7) ? tf[(ks+1)*32] : av;
                u32 a[4] = {av.x, av.y, av.z, av.w};
                #pragma unroll
                for (int n = 0; n < 8; ++n) {
                    const bf16* bp = sY + (n*8 + g)*SPB + k0 + tig*2;
                    u32 bfr[2] = {*(const u32*)bp, *(const u32*)(bp + 8)};
                    mma16816(accS[n], a, bfr);
                }
                av = nv;
            }
        }
        const int r0 = wid*16 + g;
        float z0 = __shfl_sync(0xffffffffu, accL[8][0], lane & ~3);
        float z1 = __shfl_sync(0xffffffffu, accL[8][2], lane & ~3);
        float inv0 = 0.5f / (1024.0f + SCALE_F * z0);
        float inv1 = 0.5f / (1024.0f + SCALE_F * z1);
        #pragma unroll
        for (int n = 0; n < 8; ++n) {
            int col = n*8 + tig*2;
            float2 o0 = make_float2(
                (svs[col]   + SCALE_F*accL[n][0]) * inv0 + accS[n][0],
                (svs[col+1] + SCALE_F*accL[n][1]) * inv0 + accS[n][1]);
            *(float2*)(out + (b*NL + l0 + r0)*HE + h*NE + col) = o0;
            float2 o1 = make_float2(
                (svs[col]   + SCALE_F*accL[n][2]) * inv1 + accS[n][2],
                (svs[col+1] + SCALE_F*accL[n][3]) * inv1 + accS[n][3]);
            *(float2*)(out + (b*NL + l0 + r0 + 8)*HE + h*NE + col) = o1;
        }
        if (ti < 3) {
            CPA_WAIT0();
            __syncthreads();
            p ^= 1;
        }
    }
}

// ===================== mega kernel =====================
__global__ void __launch_bounds__(256, 2) k_mega(const float* __restrict__ wre,
                                                 const float* __restrict__ wim,
                                                 const float* __restrict__ kin,
                                                 const float* __restrict__ vin,
                                                 const float* __restrict__ q,
                                                 float* __restrict__ out) {
    extern __shared__ char dyns[];
    __shared__ u32 csb[1024];
    __shared__ unsigned s_sense;
    const int t = threadIdx.x;
    const int nb = gridDim.x;
    const int bx = blockIdx.x;

    if (t == 0) s_sense = g_sns;
    #pragma unroll
    for (int r = 0; r < 4; ++r) {
        int j = r*256 + t;
        float s, c;
        sincospif((float)j * (1.0f/512.0f), &s, &c);
        csb[j] = pkbf(c, s);
    }
    __syncthreads();

    auto gridbar = [&]() {
        __threadfence();
        __syncthreads();
        if (t == 0) {
            unsigned s = s_sense ^ 1u;
            s_sense = s;
            unsigned old = atomicAdd(&g_cnt, 1u);
            if (old == (unsigned)nb - 1u) {
                g_cnt = 0;
                __threadfence();
                g_sns = s;
            } else {
                while (g_sns != s) { __nanosleep(64); }
            }
            __threadfence();
        }
        __syncthreads();
    };

    // phase 0: wt(512) | Tml(32) | Tfrag(64)
    for (int u = bx; u < 608; u += nb) {
        if (u < 512)      dev_wt(u, dyns, wre, wim, t);
        else if (u < 544) dev_tml(u - 512, csb, t);
        else              dev_tfrag(u - 544, csb, t);
        __syncthreads();
    }
    gridbar();
    // phase 1: stats(512) | fdft(512)
    for (int u = bx; u < 1024; u += nb) {
        if (u < 512) dev_stats(u, dyns, kin, vin, t);
        else         dev_fdft(u - 512, dyns, q, t);
        __syncthreads();
    }
    gridbar();
    // phase 2: mix(512) | merge(128)
    for (int u = bx; u < 640; u += nb) {
        if (u < 512) dev_mix(u, dyns, t);
        else         dev_merge(u - 512, t);
        __syncthreads();
    }
    gridbar();
    // phase 3: fused(256)
    for (int u = bx; u < 256; u += nb)
        dev_fused(u, dyns, out, t);
}

// ===================== launch =====================
extern "C" void kernel_launch(void* const* d_in, const int* in_sizes, int n_in,
                              void* d_out, int out_size) {
    (void)in_sizes; (void)n_in; (void)out_size;
    const float* q   = (const float*)d_in[0];
    const float* k   = (const float*)d_in[1];
    const float* v   = (const float*)d_in[2];
    // d_in[3] = mask (present -> reference applies no masking); unused
    const float* wre = (const float*)d_in[4];
    const float* wim = (const float*)d_in[5];
    float* out = (float*)d_out;

    static int grid = 0;
    if (!grid) {
        cudaFuncSetAttribute(k_mega, cudaFuncAttributeMaxDynamicSharedMemorySize, MEGA_SMEM);
        int nsm = 0;
        cudaDeviceGetAttribute(&nsm, cudaDevAttrMultiProcessorCount, 0);
        if (nsm < 1) nsm = 1;
        int occ = 0;
        cudaOccupancyMaxActiveBlocksPerMultiprocessor(&occ, k_mega, 256, MEGA_SMEM);
        if (occ < 1) occ = 1;
        long g = (long)occ * nsm;              // guaranteed co-resident -> barrier is safe
        if (g > 256) g = 256;
        if (g < 1) g = 1;
        grid = (int)g;
    }
    k_mega<<<grid, 256, MEGA_SMEM>>>(wre, wim, k, v, q, out);
}

// round 14
// speedup vs baseline: 1.1529x; 1.0744x over previous
#include <cuda_runtime.h>
#include <cuda_bf16.h>

#define NB 16
#define NL 1024
#define NH 8
#define NE 64
#define NM 64
#define NBH (NB*NH)
#define HE 512
#define SCALE_F 3.814697265625e-06f  // 1/(512*512)

typedef unsigned long long u64;
typedef unsigned u32;
typedef __nv_bfloat16 bf16;

// -------- scratch (static device globals) --------
static __device__ __align__(16) bf16 g_Mtp[4*NBH*NE*NE];   // K-split x4 bf16 partials of M^T
static __device__ float g_ksp[4*NBH*NE];
static __device__ float g_vsp[4*NBH*NE];
static __device__ __align__(16) bf16 g_X[4*NBH*128*64];
static __device__ __align__(16) bf16 g_Mtb[NBH*NE*NE];
static __device__ float g_ks[NBH*NE];
static __device__ float g_vs[NBH*NE];
static __device__ __align__(16) bf16 g_qb[NBH*NL*NE];
static __device__ __align__(16) bf16 g_Yt[NBH*64*128];
static __device__ __align__(16) bf16 g_Tml[128*1024];
static __device__ uint4 g_Tfrag[8*8*8*32];
static __device__ u32 g_WtR[NH*64*64*64];                  // [h][m][i][o] u32=(bf16 Wr, bf16 Wi)

// -------- global barrier state --------
static __device__ unsigned g_cnt = 0;
static __device__ volatile unsigned g_sns = 0;

// ---------------- helpers ----------------
__device__ __forceinline__ void mma16816(float* d, const u32* a, const u32* b) {
    asm volatile(
        "mma.sync.aligned.m16n8k16.row.col.f32.bf16.bf16.f32 "
        "{%0,%1,%2,%3}, {%4,%5,%6,%7}, {%8,%9}, {%0,%1,%2,%3};"
        : "+f"(d[0]), "+f"(d[1]), "+f"(d[2]), "+f"(d[3])
        : "r"(a[0]), "r"(a[1]), "r"(a[2]), "r"(a[3]), "r"(b[0]), "r"(b[1]));
}
__device__ __forceinline__ u32 pkbf(float a, float b) {
    __nv_bfloat162 p = __floats2bfloat162_rn(a, b);
    return *(u32*)&p;
}
__device__ __forceinline__ void cpa16(u32 saddr, const void* g) {
    asm volatile("cp.async.cg.shared.global [%0], [%1], 16;" :: "r"(saddr), "l"(g));
}
#define CPA_COMMIT() asm volatile("cp.async.commit_group;" ::: "memory")
#define CPA_WAIT0()  asm volatile("cp.async.wait_group 0;" ::: "memory")

#define SPA 72
#define SPB 136

#define FQ0_OFF 0
#define FQ1_OFF 18432
#define FM_OFF  36864
#define FY_OFF  47232
#define FV_OFF  64640
#define MEGA_SMEM 64896

// ===================== unit: weight transpose (WtR only) =====================
__device__ void dev_wt(int u, char* dyns, const float* __restrict__ wre,
                       const float* __restrict__ wim, int t) {
    float* smr = (float*)dyns;            // [64][65]
    float* smi = smr + 64*65;
    const int h = u >> 6, i = u & 63;
    const float* pr = wre + (size_t)u * 4096;
    const float* pq = wim + (size_t)u * 4096;
    #pragma unroll
    for (int it = 0; it < 4; ++it) {
        int idx = it * 256 + t;
        int o = idx >> 4, m4 = idx & 15;
        float4 vr = *(const float4*)(pr + o*64 + m4*4);
        float4 vi = *(const float4*)(pq + o*64 + m4*4);
        smr[o*65 + m4*4+0] = vr.x; smr[o*65 + m4*4+1] = vr.y;
        smr[o*65 + m4*4+2] = vr.z; smr[o*65 + m4*4+3] = vr.w;
        smi[o*65 + m4*4+0] = vi.x; smi[o*65 + m4*4+1] = vi.y;
        smi[o*65 + m4*4+2] = vi.z; smi[o*65 + m4*4+3] = vi.w;
    }
    __syncthreads();
    #pragma unroll
    for (int it = 0; it < 16; ++it) {
        int idx = it * 256 + t;
        int m = idx >> 6, o = idx & 63;
        g_WtR[((h*64 + m)*64 + i)*64 + o] = pkbf(smr[o*65 + m], smi[o*65 + m]);
    }
}

// ===================== unit: Tml gen (32 units) =====================
__device__ void dev_tml(int u, const u32* csb, int t) {
    #pragma unroll
    for (int r = 0; r < 16; ++r) {
        int idx = r*256 + t;
        int mr = u*4 + (idx >> 10), l = idx & 1023;
        int m = mr >> 1;
        u32 v = csb[(m*l) & 1023];
        g_Tml[mr*1024 + l] = ((const bf16*)&v)[mr & 1];
    }
}

// ===================== unit: Tfrag gen (64 units) =====================
__device__ void dev_tfrag(int u, const u32* csb, int t) {
    int idx = u*256 + t;
    int lt = idx >> 11, wid = (idx >> 8) & 7, ks = (idx >> 5) & 7, lane = idx & 31;
    int g = lane >> 2, tig = lane & 3;
    int rr = lt*128 + wid*16 + g;
    int m = ks*8 + tig;
    uint4 v;
    v.x = csb[(m*rr) & 1023];
    v.y = csb[(m*(rr+8)) & 1023];
    v.z = csb[((m+4)*rr) & 1023];
    v.w = csb[((m+4)*(rr+8)) & 1023];
    g_Tfrag[idx] = v;
}

// ===================== unit: stats (512 units) =====================
__device__ void dev_stats(int u, char* dyns, const float* __restrict__ kin,
                          const float* __restrict__ vin, int t) {
    bf16* sV = (bf16*)dyns;               // [64][SPA]
    bf16* sK = sV + 64*SPA;
    float* red = (float*)(sK + 64*SPA);   // [256]
    const int bh = u >> 2, ky = u & 3;
    const int b = bh >> 3, h = bh & 7;
    const int wid = t >> 5, lane = t & 31, g = lane >> 2, tig = lane & 3;
    const int ot = wid >> 1, eh = wid & 1;
    const int base = b * NL * HE + h * NE + ky * 256 * HE;
    const int s0 = t >> 6, o0 = t & 63;
    float pk[16], pv[16];
    #pragma unroll
    for (int it = 0; it < 16; ++it) {
        int off = base + (s0 + it*4)*HE + o0;
        pk[it] = kin[off];
        pv[it] = vin[off];
    }
    float ka = 0.f, va = 0.f;
    float acc[4][4] = {};
    for (int c = 0; c < 4; ++c) {
        __syncthreads();
        #pragma unroll
        for (int it = 0; it < 16; ++it) {
            int s = s0 + it*4;
            sK[o0*SPA + s] = __float2bfloat16(pk[it]);
            sV[o0*SPA + s] = __float2bfloat16(pv[it]);
            ka += pk[it]; va += pv[it];
        }
        if (c < 3) {
            #pragma unroll
            for (int it = 0; it < 16; ++it) {
                int off = base + ((c+1)*64 + s0 + it*4)*HE + o0;
                pk[it] = kin[off];
                pv[it] = vin[off];
            }
        }
        __syncthreads();
        #pragma unroll
        for (int ks = 0; ks < 4; ++ks) {
            const int k0 = ks * 16;
            u32 a[4];
            const bf16* ap = sV + (ot*16 + g)*SPA + k0 + tig*2;
            a[0] = *(const u32*)ap;
            a[1] = *(const u32*)(ap + 8*SPA);
            a[2] = *(const u32*)(ap + 8);
            a[3] = *(const u32*)(ap + 8*SPA + 8);
            #pragma unroll
            for (int n = 0; n < 4; ++n) {
                const bf16* bp = sK + (eh*32 + n*8 + g)*SPA + k0 + tig*2;
                u32 bfr[2] = {*(const u32*)bp, *(const u32*)(bp + 8)};
                mma16816(acc[n], a, bfr);
            }
        }
    }
    bf16* Mo = g_Mtp + (bh*4 + ky) * 4096;
    const int oo0 = ot*16 + g;
    #pragma unroll
    for (int n = 0; n < 4; ++n) {
        int col = eh*32 + n*8 + tig*2;
        *(u32*)(Mo + oo0*64 + col)     = pkbf(acc[n][0], acc[n][1]);
        *(u32*)(Mo + (oo0+8)*64 + col) = pkbf(acc[n][2], acc[n][3]);
    }
    __syncthreads();
    red[t] = ka; __syncthreads();
    if (t < 64) g_ksp[(bh*4+ky)*64 + t] = red[t] + red[t+64] + red[t+128] + red[t+192];
    __syncthreads();
    red[t] = va; __syncthreads();
    if (t < 64) g_vsp[(bh*4+ky)*64 + t] = red[t] + red[t+64] + red[t+128] + red[t+192];
}

// ===================== unit: forward DFT (512 units) =====================
__device__ void dev_fdft(int u, char* dyns, const float* __restrict__ q, int t) {
    bf16* sA = (bf16*)dyns;               // [128][SPA]
    bf16* sB = sA + 128*SPA;              // [64][SPA]
    const int bh = u >> 2, ky = u & 3;
    const int b = bh >> 3, h = bh & 7;
    const int wid = t >> 5, lane = t & 31, g = lane >> 2, tig = lane & 3;
    const int base = b * NL * HE + h * NE;
    const int l00 = t >> 6, e0 = t & 63;
    float pq[16];
    #pragma unroll
    for (int it = 0; it < 16; ++it)
        pq[it] = q[base + (ky*256 + l00 + it*4)*HE + e0];
    float acc[8][4] = {};
    bf16* qbb = g_qb + bh*(NL*NE);
    for (int c = 0; c < 4; ++c) {
        const int cc = ky*4 + c;
        __syncthreads();
        #pragma unroll
        for (int it = 0; it < 16; ++it) {
            int idx = it * 256 + t;
            int row = idx >> 5, w = idx & 31;
            ((u32*)(sA + row*SPA))[w] = ((const u32*)(g_Tml + row*1024 + cc*64))[w];
        }
        #pragma unroll
        for (int it = 0; it < 16; ++it) {
            bf16 bv = __float2bfloat16(pq[it]);
            sB[e0*SPA + (l00 + it*4)] = bv;
            qbb[(ky*256 + c*64 + l00 + it*4)*64 + e0] = bv;
        }
        if (c < 3) {
            #pragma unroll
            for (int it = 0; it < 16; ++it)
                pq[it] = q[base + (ky*256 + (c+1)*64 + l00 + it*4)*HE + e0];
        }
        __syncthreads();
        #pragma unroll
        for (int ks = 0; ks < 4; ++ks) {
            const int k0 = ks * 16;
            u32 a[4];
            const bf16* ap = sA + (wid*16 + g)*SPA + k0 + tig*2;
            a[0] = *(const u32*)ap;
            a[1] = *(const u32*)(ap + 8*SPA);
            a[2] = *(const u32*)(ap + 8);
            a[3] = *(const u32*)(ap + 8*SPA + 8);
            #pragma unroll
            for (int n = 0; n < 8; ++n) {
                const bf16* bp = sB + (n*8 + g)*SPA + k0 + tig*2;
                u32 bfr[2] = {*(const u32*)bp, *(const u32*)(bp + 8)};
                mma16816(acc[n], a, bfr);
            }
        }
    }
    bf16* Xb = g_X + (bh*4 + ky) * 8192;
    const int m0 = wid*16 + g;
    #pragma unroll
    for (int n = 0; n < 8; ++n) {
        int col = n*8 + tig*2;
        *(u32*)(Xb + m0*64 + col)     = pkbf(acc[n][0], acc[n][1]);
        *(u32*)(Xb + (m0+8)*64 + col) = pkbf(acc[n][2], acc[n][3]);
    }
}

// ===================== unit: mix (512 units; 8-warp MMA; WtI derived) =====================
__device__ void dev_mix(int u, char* dyns, int t) {
    bf16* sA  = (bf16*)dyns;              // [16][SPB]
    bf16* sBr = sA + 16*SPB;              // [64][SPB]
    bf16* sBi = sBr + 64*SPB;             // [64][SPB]
    const int h = u >> 6, m = u & 63;
    const int wid = t >> 5, lane = t & 31, g = lane >> 2, tig = lane & 3;
    #pragma unroll
    for (int it = 0; it < 4; ++it) {
        int idx = it * 256 + t;
        int bb = idx >> 6, i = idx & 63;
        const bf16* X0 = g_X + ((bb*8 + h)*4)*8192 + (2*m)*64;
        float xc = 0.f, xs = 0.f;
        #pragma unroll
        for (int ky = 0; ky < 4; ++ky) {
            xc += __bfloat162float(X0[ky*8192 + i]);
            xs += __bfloat162float(X0[ky*8192 + 64 + i]);
        }
        *(u32*)&sA[bb*SPB + 2*i] = pkbf(xc, xs);
    }
    const u32* WR = g_WtR + (h*64 + m)*4096;
    #pragma unroll
    for (int it = 0; it < 16; ++it) {
        int idx = it * 256 + t;
        int i = idx >> 6, o = idx & 63;
        u32 br = WR[i*64 + o];
        *(u32*)&sBr[o*SPB + 2*i] = br;
        // (wi, -wr): swap halves, flip sign of high bf16 — bit-identical to pkbf(wi,-wr)
        *(u32*)&sBi[o*SPB + 2*i] = __byte_perm(br, br, 0x1032) ^ 0x80000000u;
    }
    __syncthreads();
    float acc[2][4] = {};
    const int orow = wid*8 + g;
    #pragma unroll
    for (int ks = 0; ks < 8; ++ks) {
        const int k0 = ks * 16;
        u32 a[4];
        const bf16* ap = &sA[g*SPB + k0 + tig*2];
        a[0] = *(const u32*)ap;
        a[1] = *(const u32*)(ap + 8*SPB);
        a[2] = *(const u32*)(ap + 8);
        a[3] = *(const u32*)(ap + 8*SPB + 8);
        const bf16* brp = &sBr[orow*SPB + k0 + tig*2];
        u32 br[2] = {*(const u32*)brp, *(const u32*)(brp + 8)};
        mma16816(acc[0], a, br);
        const bf16* bip = &sBi[orow*SPB + k0 + tig*2];
        u32 bi2[2] = {*(const u32*)bip, *(const u32*)(bip + 8)};
        mma16816(acc[1], a, bi2);
    }
    const float f = (m == 0 ? 1.0f : 2.0f) * (1.0f / 2048.0f);
    u32* Yt32 = (u32*)g_Yt;
    #pragma unroll
    for (int cc = 0; cc < 2; ++cc) {
        int o = wid*8 + tig*2 + cc;
        Yt32[((g*8 + h)*64 + o)*64 + m]     = pkbf(f*acc[0][cc],   -f*acc[1][cc]);
        Yt32[(((g+8)*8 + h)*64 + o)*64 + m] = pkbf(f*acc[0][cc+2], -f*acc[1][cc+2]);
    }
}

// ===================== unit: merge (128 units) =====================
__device__ void dev_merge(int u, int t) {
    const u32* Mp = (const u32*)(g_Mtp + u*4*4096);
    u32* Mo = (u32*)(g_Mtb + u*4096);
    for (int idx = t; idx < 2048; idx += 256) {
        float sl = 0.f, sh = 0.f;
        #pragma unroll
        for (int ky = 0; ky < 4; ++ky) {
            u32 v = Mp[ky*2048 + idx];
            sl += __bfloat162float(((const bf16*)&v)[0]);
            sh += __bfloat162float(((const bf16*)&v)[1]);
        }
        Mo[idx] = pkbf(sl, sh);
    }
    if (t < 64) {
        const float* kp = g_ksp + u*4*64;
        const float* vp = g_vsp + u*4*64;
        g_ks[u*64 + t] = kp[t] + kp[64+t] + kp[128+t] + kp[192+t];
        g_vs[u*64 + t] = vp[t] + vp[64+t] + vp[128+t] + vp[192+t];
    }
}

// ===================== unit: fused (256 units) =====================
__device__ void dev_fused(int u, char* dyns, float* __restrict__ out, int t) {
    bf16*  sQ0 = (bf16*)(dyns + FQ0_OFF);
    bf16*  sQ1 = (bf16*)(dyns + FQ1_OFF);
    bf16*  sMt = (bf16*)(dyns + FM_OFF);
    bf16*  sY  = (bf16*)(dyns + FY_OFF);
    float* svs = (float*)(dyns + FV_OFF);
    const int bh = u & 127;
    const int half = u >> 7;
    const int b = bh >> 3, h = bh & 7;
    const int wid = t >> 5, lane = t & 31, g = lane >> 2, tig = lane & 3;
    const bf16* qbb = g_qb + bh*(NL*NE);

    #pragma unroll
    for (int r = 0; r < 2; ++r) {
        int idx = r*256 + t;
        int row = idx >> 3, w = idx & 7;
        u32 sa = (u32)__cvta_generic_to_shared(sMt + row*SPA) + w*16;
        cpa16(sa, (const char*)(g_Mtb + bh*4096 + row*64) + w*16);
    }
    #pragma unroll
    for (int r = 0; r < 4; ++r) {
        int idx = r*256 + t;
        int row = idx >> 4, w = idx & 15;
        u32 sa = (u32)__cvta_generic_to_shared(sY + row*SPB) + w*16;
        cpa16(sa, (const char*)(g_Yt + bh*8192 + row*128) + w*16);
    }
    {
        const int l0 = half * 512;
        #pragma unroll
        for (int r = 0; r < 4; ++r) {
            int idx = r*256 + t;
            int row = idx >> 3, w = idx & 7;
            u32 sa = (u32)__cvta_generic_to_shared(sQ0 + row*SPA) + w*16;
            cpa16(sa, (const char*)(qbb + (l0 + row)*64) + w*16);
        }
    }
    if (t < 64) {
        sMt[64*SPA + t] = __float2bfloat16(g_ks[bh*64 + t]);
        svs[t] = g_vs[bh*64 + t];
    }
    for (int idx = t; idx < 7*SPA; idx += 256)
        sMt[65*SPA + idx] = __float2bfloat16(0.f);
    CPA_COMMIT();
    CPA_WAIT0();
    __syncthreads();

    bf16* sQb[2] = {sQ0, sQ1};
    int p = 0;
    for (int ti = 0; ti < 4; ++ti) {
        const int lt = half*4 + ti;
        const int l0 = lt * 128;
        if (ti < 3) {
            const int l1 = half*512 + (ti+1)*128;
            #pragma unroll
            for (int r = 0; r < 4; ++r) {
                int idx = r*256 + t;
                int row = idx >> 3, w = idx & 7;
                u32 sa = (u32)__cvta_generic_to_shared(sQb[p^1] + row*SPA) + w*16;
                cpa16(sa, (const char*)(qbb + (l1 + row)*64) + w*16);
            }
            CPA_COMMIT();
        }
        const bf16* sQ = sQb[p];
        float accL[9][4] = {};
        float accS[8][4] = {};
        #pragma unroll
        for (int ks = 0; ks < 4; ++ks) {
            const int k0 = ks * 16;
            u32 a[4];
            const bf16* ap = sQ + (wid*16 + g)*SPA + k0 + tig*2;
            a[0] = *(const u32*)ap;
            a[1] = *(const u32*)(ap + 8*SPA);
            a[2] = *(const u32*)(ap + 8);
            a[3] = *(const u32*)(ap + 8*SPA + 8);
            #pragma unroll
            for (int n = 0; n < 9; ++n) {
                const bf16* bp = sMt + (n*8 + g)*SPA + k0 + tig*2;
                u32 bfr[2] = {*(const u32*)bp, *(const u32*)(bp + 8)};
                mma16816(accL[n], a, bfr);
            }
        }
        {
            const uint4* tf = g_Tfrag + ((lt*8 + wid)*8)*32 + lane;
            uint4 av = tf[0];
            #pragma unroll
            for (int ks = 0; ks < 8; ++ks) {
                const int k0 = ks * 16;
                uint4 nv = (ks < 7) ? tf[(ks+1)*32] : av;
                u32 a[4] = {av.x, av.y, av.z, av.w};
                #pragma unroll
                for (int n = 0; n < 8; ++n) {
                    const bf16* bp = sY + (n*8 + g)*SPB + k0 + tig*2;
                    u32 bfr[2] = {*(const u32*)bp, *(const u32*)(bp + 8)};
                    mma16816(accS[n], a, bfr);
                }
                av = nv;
            }
        }
        const int r0 = wid*16 + g;
        float z0 = __shfl_sync(0xffffffffu, accL[8][0], lane & ~3);
        float z1 = __shfl_sync(0xffffffffu, accL[8][2], lane & ~3);
        float inv0 = 0.5f / (1024.0f + SCALE_F * z0);
        float inv1 = 0.5f / (1024.0f + SCALE_F * z1);
        #pragma unroll
        for (int n = 0; n < 8; ++n) {
            int col = n*8 + tig*2;
            float2 o0 = make_float2(
                (svs[col]   + SCALE_F*accL[n][0]) * inv0 + accS[n][0],
                (svs[col+1] + SCALE_F*accL[n][1]) * inv0 + accS[n][1]);
            *(float2*)(out + (b*NL + l0 + r0)*HE + h*NE + col) = o0;
            float2 o1 = make_float2(
                (svs[col]   + SCALE_F*accL[n][2]) * inv1 + accS[n][2],
                (svs[col+1] + SCALE_F*accL[n][3]) * inv1 + accS[n][3]);
            *(float2*)(out + (b*NL + l0 + r0 + 8)*HE + h*NE + col) = o1;
        }
        if (ti < 3) {
            CPA_WAIT0();
            __syncthreads();
            p ^= 1;
        }
    }
}

// ===================== mega kernel =====================
__global__ void __launch_bounds__(256, 2) k_mega(const float* __restrict__ wre,
                                                 const float* __restrict__ wim,
                                                 const float* __restrict__ kin,
                                                 const float* __restrict__ vin,
                                                 const float* __restrict__ q,
                                                 float* __restrict__ out) {
    extern __shared__ char dyns[];
    __shared__ u32 csb[1024];
    __shared__ unsigned s_sense;
    const int t = threadIdx.x;
    const int nb = gridDim.x;
    const int bx = blockIdx.x;

    if (t == 0) s_sense = g_sns;
    #pragma unroll
    for (int r = 0; r < 4; ++r) {
        int j = r*256 + t;
        float s, c;
        sincospif((float)j * (1.0f/512.0f), &s, &c);
        csb[j] = pkbf(c, s);
    }
    __syncthreads();

    auto gridbar = [&]() {
        __threadfence();
        __syncthreads();
        if (t == 0) {
            unsigned s = s_sense ^ 1u;
            s_sense = s;
            unsigned old = atomicAdd(&g_cnt, 1u);
            if (old == (unsigned)nb - 1u) {
                g_cnt = 0;
                __threadfence();
                g_sns = s;
            } else {
                while (g_sns != s) { __nanosleep(64); }
            }
            __threadfence();
        }
        __syncthreads();
    };

    // phase 0: wt(512) | Tml(32) | Tfrag(64)
    for (int u = bx; u < 608; u += nb) {
        if (u < 512)      dev_wt(u, dyns, wre, wim, t);
        else if (u < 544) dev_tml(u - 512, csb, t);
        else              dev_tfrag(u - 544, csb, t);
        __syncthreads();
    }
    gridbar();
    // phase 1: stats(512) | fdft(512)
    for (int u = bx; u < 1024; u += nb) {
        if (u < 512) dev_stats(u, dyns, kin, vin, t);
        else         dev_fdft(u - 512, dyns, q, t);
        __syncthreads();
    }
    gridbar();
    // phase 2: mix(512) | merge(128)
    for (int u = bx; u < 640; u += nb) {
        if (u < 512) dev_mix(u, dyns, t);
        else         dev_merge(u - 512, t);
        __syncthreads();
    }
    gridbar();
    // phase 3: fused(256)
    for (int u = bx; u < 256; u += nb)
        dev_fused(u, dyns, out, t);
}

// ===================== launch =====================
extern "C" void kernel_launch(void* const* d_in, const int* in_sizes, int n_in,
                              void* d_out, int out_size) {
    (void)in_sizes; (void)n_in; (void)out_size;
    const float* q   = (const float*)d_in[0];
    const float* k   = (const float*)d_in[1];
    const float* v   = (const float*)d_in[2];
    // d_in[3] = mask (present -> reference applies no masking); unused
    const float* wre = (const float*)d_in[4];
    const float* wim = (const float*)d_in[5];
    float* out = (float*)d_out;

    static int grid = 0;
    if (!grid) {
        cudaFuncSetAttribute(k_mega, cudaFuncAttributeMaxDynamicSharedMemorySize, MEGA_SMEM);
        int nsm = 0;
        cudaDeviceGetAttribute(&nsm, cudaDevAttrMultiProcessorCount, 0);
        if (nsm < 1) nsm = 1;
        int occ = 0;
        cudaOccupancyMaxActiveBlocksPerMultiprocessor(&occ, k_mega, 256, MEGA_SMEM);
        if (occ < 1) occ = 1;
        long g = (long)occ * nsm;
        if (g > 256) g = 256;
        if (g < 1) g = 1;
        grid = (int)g;
    }
    k_mega<<<grid, 256, MEGA_SMEM>>>(wre, wim, k, v, q, out);
}

// round 15
// speedup vs baseline: 1.1532x; 1.0003x over previous
#include <cuda_runtime.h>
#include <cuda_bf16.h>

#define NB 16
#define NL 1024
#define NH 8
#define NE 64
#define NM 64
#define NBH (NB*NH)
#define HE 512
#define SCALE_F 3.814697265625e-06f  // 1/(512*512)

typedef unsigned long long u64;
typedef unsigned u32;
typedef __nv_bfloat16 bf16;

// -------- scratch (static device globals) --------
static __device__ __align__(16) bf16 g_Mtp[4*NBH*NE*NE];   // K-split x4 bf16 partials of M^T
static __device__ float g_ksp[4*NBH*NE];
static __device__ float g_vsp[4*NBH*NE];
static __device__ __align__(16) bf16 g_X[4*NBH*128*64];
static __device__ __align__(16) bf16 g_Mtb[NBH*NE*NE];
static __device__ float g_ks[NBH*NE];
static __device__ float g_vs[NBH*NE];
static __device__ __align__(16) bf16 g_qb[NBH*NL*NE];
static __device__ __align__(16) bf16 g_Yt[NBH*64*128];
static __device__ __align__(16) bf16 g_Tml[128*1024];
static __device__ uint4 g_Tfrag[8*8*8*32];
static __device__ u32 g_WtR[NH*64*64*64];                  // [h][m][i][o] u32=(bf16 Wr, bf16 Wi)

// -------- global barrier state --------
static __device__ unsigned g_cnt = 0;
static __device__ volatile unsigned g_sns = 0;

// ---------------- helpers ----------------
__device__ __forceinline__ void mma16816(float* d, const u32* a, const u32* b) {
    asm volatile(
        "mma.sync.aligned.m16n8k16.row.col.f32.bf16.bf16.f32 "
        "{%0,%1,%2,%3}, {%4,%5,%6,%7}, {%8,%9}, {%0,%1,%2,%3};"
        : "+f"(d[0]), "+f"(d[1]), "+f"(d[2]), "+f"(d[3])
        : "r"(a[0]), "r"(a[1]), "r"(a[2]), "r"(a[3]), "r"(b[0]), "r"(b[1]));
}
__device__ __forceinline__ u32 pkbf(float a, float b) {
    __nv_bfloat162 p = __floats2bfloat162_rn(a, b);
    return *(u32*)&p;
}
__device__ __forceinline__ void cpa16(u32 saddr, const void* g) {
    asm volatile("cp.async.cg.shared.global [%0], [%1], 16;" :: "r"(saddr), "l"(g));
}
#define CPA_COMMIT() asm volatile("cp.async.commit_group;" ::: "memory")
#define CPA_WAIT0()  asm volatile("cp.async.wait_group 0;" ::: "memory")

#define SPA 72
#define SPB 136

// front2 smem: max(wt 33280, stats 19456, fdft 27648, mix 144*SPB*2=39168)
#define FRONT2_SMEM 39168

// fused smem layout
#define FQ0_OFF 0
#define FQ1_OFF 18432
#define FM_OFF  36864
#define FY_OFF  47232
#define FV_OFF  64640
#define FUSED_SMEM 64896

// ===================== unit: weight transpose (WtR only) =====================
__device__ void dev_wt(int u, char* dyns, const float* __restrict__ wre,
                       const float* __restrict__ wim, int t) {
    float* smr = (float*)dyns;            // [64][65]
    float* smi = smr + 64*65;
    const int h = u >> 6, i = u & 63;
    const float* pr = wre + (size_t)u * 4096;
    const float* pq = wim + (size_t)u * 4096;
    #pragma unroll
    for (int it = 0; it < 4; ++it) {
        int idx = it * 256 + t;
        int o = idx >> 4, m4 = idx & 15;
        float4 vr = *(const float4*)(pr + o*64 + m4*4);
        float4 vi = *(const float4*)(pq + o*64 + m4*4);
        smr[o*65 + m4*4+0] = vr.x; smr[o*65 + m4*4+1] = vr.y;
        smr[o*65 + m4*4+2] = vr.z; smr[o*65 + m4*4+3] = vr.w;
        smi[o*65 + m4*4+0] = vi.x; smi[o*65 + m4*4+1] = vi.y;
        smi[o*65 + m4*4+2] = vi.z; smi[o*65 + m4*4+3] = vi.w;
    }
    __syncthreads();
    #pragma unroll
    for (int it = 0; it < 16; ++it) {
        int idx = it * 256 + t;
        int m = idx >> 6, o = idx & 63;
        g_WtR[((h*64 + m)*64 + i)*64 + o] = pkbf(smr[o*65 + m], smi[o*65 + m]);
    }
}

// ===================== unit: Tml gen (32 units) =====================
__device__ void dev_tml(int u, const u32* csb, int t) {
    #pragma unroll
    for (int r = 0; r < 16; ++r) {
        int idx = r*256 + t;
        int mr = u*4 + (idx >> 10), l = idx & 1023;
        int m = mr >> 1;
        u32 v = csb[(m*l) & 1023];
        g_Tml[mr*1024 + l] = ((const bf16*)&v)[mr & 1];
    }
}

// ===================== unit: Tfrag gen (64 units) =====================
__device__ void dev_tfrag(int u, const u32* csb, int t) {
    int idx = u*256 + t;
    int lt = idx >> 11, wid = (idx >> 8) & 7, ks = (idx >> 5) & 7, lane = idx & 31;
    int g = lane >> 2, tig = lane & 3;
    int rr = lt*128 + wid*16 + g;
    int m = ks*8 + tig;
    uint4 v;
    v.x = csb[(m*rr) & 1023];
    v.y = csb[(m*(rr+8)) & 1023];
    v.z = csb[((m+4)*rr) & 1023];
    v.w = csb[((m+4)*(rr+8)) & 1023];
    g_Tfrag[idx] = v;
}

// ===================== unit: stats (512 units) =====================
__device__ void dev_stats(int u, char* dyns, const float* __restrict__ kin,
                          const float* __restrict__ vin, int t) {
    bf16* sV = (bf16*)dyns;               // [64][SPA]
    bf16* sK = sV + 64*SPA;
    float* red = (float*)(sK + 64*SPA);   // [256]
    const int bh = u >> 2, ky = u & 3;
    const int b = bh >> 3, h = bh & 7;
    const int wid = t >> 5, lane = t & 31, g = lane >> 2, tig = lane & 3;
    const int ot = wid >> 1, eh = wid & 1;
    const int base = b * NL * HE + h * NE + ky * 256 * HE;
    const int s0 = t >> 6, o0 = t & 63;
    float pk[16], pv[16];
    #pragma unroll
    for (int it = 0; it < 16; ++it) {
        int off = base + (s0 + it*4)*HE + o0;
        pk[it] = kin[off];
        pv[it] = vin[off];
    }
    float ka = 0.f, va = 0.f;
    float acc[4][4] = {};
    for (int c = 0; c < 4; ++c) {
        __syncthreads();
        #pragma unroll
        for (int it = 0; it < 16; ++it) {
            int s = s0 + it*4;
            sK[o0*SPA + s] = __float2bfloat16(pk[it]);
            sV[o0*SPA + s] = __float2bfloat16(pv[it]);
            ka += pk[it]; va += pv[it];
        }
        if (c < 3) {
            #pragma unroll
            for (int it = 0; it < 16; ++it) {
                int off = base + ((c+1)*64 + s0 + it*4)*HE + o0;
                pk[it] = kin[off];
                pv[it] = vin[off];
            }
        }
        __syncthreads();
        #pragma unroll
        for (int ks = 0; ks < 4; ++ks) {
            const int k0 = ks * 16;
            u32 a[4];
            const bf16* ap = sV + (ot*16 + g)*SPA + k0 + tig*2;
            a[0] = *(const u32*)ap;
            a[1] = *(const u32*)(ap + 8*SPA);
            a[2] = *(const u32*)(ap + 8);
            a[3] = *(const u32*)(ap + 8*SPA + 8);
            #pragma unroll
            for (int n = 0; n < 4; ++n) {
                const bf16* bp = sK + (eh*32 + n*8 + g)*SPA + k0 + tig*2;
                u32 bfr[2] = {*(const u32*)bp, *(const u32*)(bp + 8)};
                mma16816(acc[n], a, bfr);
            }
        }
    }
    bf16* Mo = g_Mtp + (bh*4 + ky) * 4096;
    const int oo0 = ot*16 + g;
    #pragma unroll
    for (int n = 0; n < 4; ++n) {
        int col = eh*32 + n*8 + tig*2;
        *(u32*)(Mo + oo0*64 + col)     = pkbf(acc[n][0], acc[n][1]);
        *(u32*)(Mo + (oo0+8)*64 + col) = pkbf(acc[n][2], acc[n][3]);
    }
    __syncthreads();
    red[t] = ka; __syncthreads();
    if (t < 64) g_ksp[(bh*4+ky)*64 + t] = red[t] + red[t+64] + red[t+128] + red[t+192];
    __syncthreads();
    red[t] = va; __syncthreads();
    if (t < 64) g_vsp[(bh*4+ky)*64 + t] = red[t] + red[t+64] + red[t+128] + red[t+192];
}

// ===================== unit: forward DFT (512 units) =====================
__device__ void dev_fdft(int u, char* dyns, const float* __restrict__ q, int t) {
    bf16* sA = (bf16*)dyns;               // [128][SPA]
    bf16* sB = sA + 128*SPA;              // [64][SPA]
    const int bh = u >> 2, ky = u & 3;
    const int b = bh >> 3, h = bh & 7;
    const int wid = t >> 5, lane = t & 31, g = lane >> 2, tig = lane & 3;
    const int base = b * NL * HE + h * NE;
    const int l00 = t >> 6, e0 = t & 63;
    float pq[16];
    #pragma unroll
    for (int it = 0; it < 16; ++it)
        pq[it] = q[base + (ky*256 + l00 + it*4)*HE + e0];
    float acc[8][4] = {};
    bf16* qbb = g_qb + bh*(NL*NE);
    for (int c = 0; c < 4; ++c) {
        const int cc = ky*4 + c;
        __syncthreads();
        #pragma unroll
        for (int it = 0; it < 16; ++it) {
            int idx = it * 256 + t;
            int row = idx >> 5, w = idx & 31;
            ((u32*)(sA + row*SPA))[w] = ((const u32*)(g_Tml + row*1024 + cc*64))[w];
        }
        #pragma unroll
        for (int it = 0; it < 16; ++it) {
            bf16 bv = __float2bfloat16(pq[it]);
            sB[e0*SPA + (l00 + it*4)] = bv;
            qbb[(ky*256 + c*64 + l00 + it*4)*64 + e0] = bv;
        }
        if (c < 3) {
            #pragma unroll
            for (int it = 0; it < 16; ++it)
                pq[it] = q[base + (ky*256 + (c+1)*64 + l00 + it*4)*HE + e0];
        }
        __syncthreads();
        #pragma unroll
        for (int ks = 0; ks < 4; ++ks) {
            const int k0 = ks * 16;
            u32 a[4];
            const bf16* ap = sA + (wid*16 + g)*SPA + k0 + tig*2;
            a[0] = *(const u32*)ap;
            a[1] = *(const u32*)(ap + 8*SPA);
            a[2] = *(const u32*)(ap + 8);
            a[3] = *(const u32*)(ap + 8*SPA + 8);
            #pragma unroll
            for (int n = 0; n < 8; ++n) {
                const bf16* bp = sB + (n*8 + g)*SPA + k0 + tig*2;
                u32 bfr[2] = {*(const u32*)bp, *(const u32*)(bp + 8)};
                mma16816(acc[n], a, bfr);
            }
        }
    }
    bf16* Xb = g_X + (bh*4 + ky) * 8192;
    const int m0 = wid*16 + g;
    #pragma unroll
    for (int n = 0; n < 8; ++n) {
        int col = n*8 + tig*2;
        *(u32*)(Xb + m0*64 + col)     = pkbf(acc[n][0], acc[n][1]);
        *(u32*)(Xb + (m0+8)*64 + col) = pkbf(acc[n][2], acc[n][3]);
    }
}

// ===================== unit: mix (512 units; 8-warp MMA; WtI derived) =====================
__device__ void dev_mix(int u, char* dyns, int t) {
    bf16* sA  = (bf16*)dyns;              // [16][SPB]
    bf16* sBr = sA + 16*SPB;              // [64][SPB]
    bf16* sBi = sBr + 64*SPB;             // [64][SPB]
    const int h = u >> 6, m = u & 63;
    const int wid = t >> 5, lane = t & 31, g = lane >> 2, tig = lane & 3;
    #pragma unroll
    for (int it = 0; it < 4; ++it) {
        int idx = it * 256 + t;
        int bb = idx >> 6, i = idx & 63;
        const bf16* X0 = g_X + ((bb*8 + h)*4)*8192 + (2*m)*64;
        float xc = 0.f, xs = 0.f;
        #pragma unroll
        for (int ky = 0; ky < 4; ++ky) {
            xc += __bfloat162float(X0[ky*8192 + i]);
            xs += __bfloat162float(X0[ky*8192 + 64 + i]);
        }
        *(u32*)&sA[bb*SPB + 2*i] = pkbf(xc, xs);
    }
    const u32* WR = g_WtR + (h*64 + m)*4096;
    #pragma unroll
    for (int it = 0; it < 16; ++it) {
        int idx = it * 256 + t;
        int i = idx >> 6, o = idx & 63;
        u32 br = WR[i*64 + o];
        *(u32*)&sBr[o*SPB + 2*i] = br;
        *(u32*)&sBi[o*SPB + 2*i] = __byte_perm(br, br, 0x1032) ^ 0x80000000u;
    }
    __syncthreads();
    float acc[2][4] = {};
    const int orow = wid*8 + g;
    #pragma unroll
    for (int ks = 0; ks < 8; ++ks) {
        const int k0 = ks * 16;
        u32 a[4];
        const bf16* ap = &sA[g*SPB + k0 + tig*2];
        a[0] = *(const u32*)ap;
        a[1] = *(const u32*)(ap + 8*SPB);
        a[2] = *(const u32*)(ap + 8);
        a[3] = *(const u32*)(ap + 8*SPB + 8);
        const bf16* brp = &sBr[orow*SPB + k0 + tig*2];
        u32 br[2] = {*(const u32*)brp, *(const u32*)(brp + 8)};
        mma16816(acc[0], a, br);
        const bf16* bip = &sBi[orow*SPB + k0 + tig*2];
        u32 bi2[2] = {*(const u32*)bip, *(const u32*)(bip + 8)};
        mma16816(acc[1], a, bi2);
    }
    const float f = (m == 0 ? 1.0f : 2.0f) * (1.0f / 2048.0f);
    u32* Yt32 = (u32*)g_Yt;
    #pragma unroll
    for (int cc = 0; cc < 2; ++cc) {
        int o = wid*8 + tig*2 + cc;
        Yt32[((g*8 + h)*64 + o)*64 + m]     = pkbf(f*acc[0][cc],   -f*acc[1][cc]);
        Yt32[(((g+8)*8 + h)*64 + o)*64 + m] = pkbf(f*acc[0][cc+2], -f*acc[1][cc+2]);
    }
}

// ===================== unit: merge (128 units) =====================
__device__ void dev_merge(int u, int t) {
    const u32* Mp = (const u32*)(g_Mtp + u*4*4096);
    u32* Mo = (u32*)(g_Mtb + u*4096);
    for (int idx = t; idx < 2048; idx += 256) {
        float sl = 0.f, sh = 0.f;
        #pragma unroll
        for (int ky = 0; ky < 4; ++ky) {
            u32 v = Mp[ky*2048 + idx];
            sl += __bfloat162float(((const bf16*)&v)[0]);
            sh += __bfloat162float(((const bf16*)&v)[1]);
        }
        Mo[idx] = pkbf(sl, sh);
    }
    if (t < 64) {
        const float* kp = g_ksp + u*4*64;
        const float* vp = g_vsp + u*4*64;
        g_ks[u*64 + t] = kp[t] + kp[64+t] + kp[128+t] + kp[192+t];
        g_vs[u*64 + t] = vp[t] + vp[64+t] + vp[128+t] + vp[192+t];
    }
}

// ===================== front kernel: phases 0-2, 3 CTAs/SM =====================
__global__ void __launch_bounds__(256, 3) k_front2(const float* __restrict__ wre,
                                                   const float* __restrict__ wim,
                                                   const float* __restrict__ kin,
                                                   const float* __restrict__ vin,
                                                   const float* __restrict__ q) {
    extern __shared__ char dyns[];
    __shared__ u32 csb[1024];
    __shared__ unsigned s_sense;
    const int t = threadIdx.x;
    const int nb = gridDim.x;
    const int bx = blockIdx.x;

    if (t == 0) s_sense = g_sns;
    #pragma unroll
    for (int r = 0; r < 4; ++r) {
        int j = r*256 + t;
        float s, c;
        sincospif((float)j * (1.0f/512.0f), &s, &c);
        csb[j] = pkbf(c, s);
    }
    __syncthreads();

    auto gridbar = [&]() {
        __threadfence();
        __syncthreads();
        if (t == 0) {
            unsigned s = s_sense ^ 1u;
            s_sense = s;
            unsigned old = atomicAdd(&g_cnt, 1u);
            if (old == (unsigned)nb - 1u) {
                g_cnt = 0;
                __threadfence();
                g_sns = s;
            } else {
                while (g_sns != s) { __nanosleep(64); }
            }
            __threadfence();
        }
        __syncthreads();
    };

    // phase 0: Tml(32) | Tfrag(64)  (tables only)
    for (int u = bx; u < 96; u += nb) {
        if (u < 32) dev_tml(u, csb, t);
        else        dev_tfrag(u - 32, csb, t);
        __syncthreads();
    }
    gridbar();
    // phase 1: wt(512) | stats(512) | fdft(512)
    for (int u = bx; u < 1536; u += nb) {
        if (u < 512)       dev_wt(u, dyns, wre, wim, t);
        else if (u < 1024) dev_stats(u - 512, dyns, kin, vin, t);
        else               dev_fdft(u - 1024, dyns, q, t);
        __syncthreads();
    }
    gridbar();
    // phase 2: mix(512) | merge(128)
    for (int u = bx; u < 640; u += nb) {
        if (u < 512) dev_mix(u, dyns, t);
        else         dev_merge(u - 512, t);
        __syncthreads();
    }
}

// ===================== fused kernel: phase 3, 2 CTAs/SM =====================
__global__ void __launch_bounds__(256, 2) k_fused(float* __restrict__ out) {
    extern __shared__ char dyns[];
    bf16*  sQ0 = (bf16*)(dyns + FQ0_OFF);
    bf16*  sQ1 = (bf16*)(dyns + FQ1_OFF);
    bf16*  sMt = (bf16*)(dyns + FM_OFF);
    bf16*  sY  = (bf16*)(dyns + FY_OFF);
    float* svs = (float*)(dyns + FV_OFF);
    const int bh = blockIdx.x;
    const int half = blockIdx.y;
    const int b = bh >> 3, h = bh & 7;
    const int t = threadIdx.x;
    const int wid = t >> 5, lane = t & 31, g = lane >> 2, tig = lane & 3;
    const bf16* qbb = g_qb + bh*(NL*NE);

    #pragma unroll
    for (int r = 0; r < 2; ++r) {
        int idx = r*256 + t;
        int row = idx >> 3, w = idx & 7;
        u32 sa = (u32)__cvta_generic_to_shared(sMt + row*SPA) + w*16;
        cpa16(sa, (const char*)(g_Mtb + bh*4096 + row*64) + w*16);
    }
    #pragma unroll
    for (int r = 0; r < 4; ++r) {
        int idx = r*256 + t;
        int row = idx >> 4, w = idx & 15;
        u32 sa = (u32)__cvta_generic_to_shared(sY + row*SPB) + w*16;
        cpa16(sa, (const char*)(g_Yt + bh*8192 + row*128) + w*16);
    }
    {
        const int l0 = half * 512;
        #pragma unroll
        for (int r = 0; r < 4; ++r) {
            int idx = r*256 + t;
            int row = idx >> 3, w = idx & 7;
            u32 sa = (u32)__cvta_generic_to_shared(sQ0 + row*SPA) + w*16;
            cpa16(sa, (const char*)(qbb + (l0 + row)*64) + w*16);
        }
    }
    if (t < 64) {
        sMt[64*SPA + t] = __float2bfloat16(g_ks[bh*64 + t]);
        svs[t] = g_vs[bh*64 + t];
    }
    for (int idx = t; idx < 7*SPA; idx += 256)
        sMt[65*SPA + idx] = __float2bfloat16(0.f);
    CPA_COMMIT();
    CPA_WAIT0();
    __syncthreads();

    bf16* sQb[2] = {sQ0, sQ1};
    int p = 0;
    for (int ti = 0; ti < 4; ++ti) {
        const int lt = half*4 + ti;
        const int l0 = lt * 128;
        if (ti < 3) {
            const int l1 = half*512 + (ti+1)*128;
            #pragma unroll
            for (int r = 0; r < 4; ++r) {
                int idx = r*256 + t;
                int row = idx >> 3, w = idx & 7;
                u32 sa = (u32)__cvta_generic_to_shared(sQb[p^1] + row*SPA) + w*16;
                cpa16(sa, (const char*)(qbb + (l1 + row)*64) + w*16);
            }
            CPA_COMMIT();
        }
        const bf16* sQ = sQb[p];
        float accL[9][4] = {};
        float accS[8][4] = {};
        #pragma unroll
        for (int ks = 0; ks < 4; ++ks) {
            const int k0 = ks * 16;
            u32 a[4];
            const bf16* ap = sQ + (wid*16 + g)*SPA + k0 + tig*2;
            a[0] = *(const u32*)ap;
            a[1] = *(const u32*)(ap + 8*SPA);
            a[2] = *(const u32*)(ap + 8);
            a[3] = *(const u32*)(ap + 8*SPA + 8);
            #pragma unroll
            for (int n = 0; n < 9; ++n) {
                const bf16* bp = sMt + (n*8 + g)*SPA + k0 + tig*2;
                u32 bfr[2] = {*(const u32*)bp, *(const u32*)(bp + 8)};
                mma16816(accL[n], a, bfr);
            }
        }
        {
            const uint4* tf = g_Tfrag + ((lt*8 + wid)*8)*32 + lane;
            uint4 av = tf[0];
            #pragma unroll
            for (int ks = 0; ks < 8; ++ks) {
                const int k0 = ks * 16;
                uint4 nv = (ks < 7) ? tf[(ks+1)*32] : av;
                u32 a[4] = {av.x, av.y, av.z, av.w};
                #pragma unroll
                for (int n = 0; n < 8; ++n) {
                    const bf16* bp = sY + (n*8 + g)*SPB + k0 + tig*2;
                    u32 bfr[2] = {*(const u32*)bp, *(const u32*)(bp + 8)};
                    mma16816(accS[n], a, bfr);
                }
                av = nv;
            }
        }
        const int r0 = wid*16 + g;
        float z0 = __shfl_sync(0xffffffffu, accL[8][0], lane & ~3);
        float z1 = __shfl_sync(0xffffffffu, accL[8][2], lane & ~3);
        float inv0 = 0.5f / (1024.0f + SCALE_F * z0);
        float inv1 = 0.5f / (1024.0f + SCALE_F * z1);
        #pragma unroll
        for (int n = 0; n < 8; ++n) {
            int col = n*8 + tig*2;
            float2 o0 = make_float2(
                (svs[col]   + SCALE_F*accL[n][0]) * inv0 + accS[n][0],
                (svs[col+1] + SCALE_F*accL[n][1]) * inv0 + accS[n][1]);
            *(float2*)(out + (b*NL + l0 + r0)*HE + h*NE + col) = o0;
            float2 o1 = make_float2(
                (svs[col]   + SCALE_F*accL[n][2]) * inv1 + accS[n][2],
                (svs[col+1] + SCALE_F*accL[n][3]) * inv1 + accS[n][3]);
            *(float2*)(out + (b*NL + l0 + r0 + 8)*HE + h*NE + col) = o1;
        }
        if (ti < 3) {
            CPA_WAIT0();
            __syncthreads();
            p ^= 1;
        }
    }
}

// ===================== launch =====================
extern "C" void kernel_launch(void* const* d_in, const int* in_sizes, int n_in,
                              void* d_out, int out_size) {
    (void)in_sizes; (void)n_in; (void)out_size;
    const float* q   = (const float*)d_in[0];
    const float* k   = (const float*)d_in[1];
    const float* v   = (const float*)d_in[2];
    // d_in[3] = mask (present -> reference applies no masking); unused
    const float* wre = (const float*)d_in[4];
    const float* wim = (const float*)d_in[5];
    float* out = (float*)d_out;

    static int grid = 0;
    if (!grid) {
        cudaFuncSetAttribute(k_front2, cudaFuncAttributeMaxDynamicSharedMemorySize, FRONT2_SMEM);
        cudaFuncSetAttribute(k_fused,  cudaFuncAttributeMaxDynamicSharedMemorySize, FUSED_SMEM);
        int nsm = 0;
        cudaDeviceGetAttribute(&nsm, cudaDevAttrMultiProcessorCount, 0);
        if (nsm < 1) nsm = 1;
        int occ = 0;
        cudaOccupancyMaxActiveBlocksPerMultiprocessor(&occ, k_front2, 256, FRONT2_SMEM);
        if (occ < 1) occ = 1;
        long g = (long)occ * nsm;          // guaranteed co-resident -> barrier safe
        if (g > 512) g = 512;
        if (g < 1) g = 1;
        grid = (int)g;
    }
    k_front2<<<grid, 256, FRONT2_SMEM>>>(wre, wim, k, v, q);
    k_fused <<<dim3(NBH, 2), 256, FUSED_SMEM>>>(out);
}

// round 16
// speedup vs baseline: 1.2053x; 1.0451x over previous
#include <cuda_runtime.h>
#include <cuda_bf16.h>

#define NB 16
#define NL 1024
#define NH 8
#define NE 64
#define NM 64
#define NBH (NB*NH)
#define HE 512
#define SCALE_F 3.814697265625e-06f  // 1/(512*512)

typedef unsigned long long u64;
typedef unsigned u32;
typedef __nv_bfloat16 bf16;

// -------- scratch (static device globals) --------
static __device__ __align__(16) bf16 g_Mtp[4*NBH*NE*NE];   // K-split x4 bf16 partials of M^T
static __device__ float g_ksp[4*NBH*NE];
static __device__ float g_vsp[4*NBH*NE];
static __device__ __align__(16) bf16 g_X[4*NBH*128*64];
static __device__ __align__(16) bf16 g_Mtb[NBH*NE*NE];
static __device__ float g_ks[NBH*NE];
static __device__ float g_vs[NBH*NE];
static __device__ __align__(16) bf16 g_qb[NBH*NL*NE];
static __device__ __align__(16) bf16 g_Yt[NBH*64*128];
static __device__ __align__(16) bf16 g_Tml[128*1024];
static __device__ uint4 g_Tfrag[8*8*8*32];
static __device__ u32 g_WtR[NH*64*64*64];                  // [h][m][i][o] u32=(bf16 Wr, bf16 Wi)

// -------- global barrier state --------
static __device__ unsigned g_cnt = 0;
static __device__ volatile unsigned g_sns = 0;

// ---------------- helpers ----------------
__device__ __forceinline__ void mma16816(float* d, const u32* a, const u32* b) {
    asm volatile(
        "mma.sync.aligned.m16n8k16.row.col.f32.bf16.bf16.f32 "
        "{%0,%1,%2,%3}, {%4,%5,%6,%7}, {%8,%9}, {%0,%1,%2,%3};"
        : "+f"(d[0]), "+f"(d[1]), "+f"(d[2]), "+f"(d[3])
        : "r"(a[0]), "r"(a[1]), "r"(a[2]), "r"(a[3]), "r"(b[0]), "r"(b[1]));
}
__device__ __forceinline__ u32 pkbf(float a, float b) {
    __nv_bfloat162 p = __floats2bfloat162_rn(a, b);
    return *(u32*)&p;
}
__device__ __forceinline__ void cpa16(u32 saddr, const void* g) {
    asm volatile("cp.async.cg.shared.global [%0], [%1], 16;" :: "r"(saddr), "l"(g));
}
#define CPA_COMMIT() asm volatile("cp.async.commit_group;" ::: "memory")
#define CPA_WAIT0()  asm volatile("cp.async.wait_group 0;" ::: "memory")

#define SPA 72
#define SPB 136

// front2 smem: max(wt 16640, stats 37888, fdft 55296, mix 21760)
#define FRONT2_SMEM 55296

// fused smem layout
#define FQ0_OFF 0
#define FQ1_OFF 18432
#define FM_OFF  36864
#define FY_OFF  47232
#define FV_OFF  64640
#define FUSED_SMEM 64896

// ===================== unit: weight transpose (bf16-packed smem) =====================
__device__ void dev_wt(int u, char* dyns, const float* __restrict__ wre,
                       const float* __restrict__ wim, int t) {
    u32* smw = (u32*)dyns;                // [64][65]
    const int h = u >> 6, i = u & 63;
    const float* pr = wre + (size_t)u * 4096;
    const float* pq = wim + (size_t)u * 4096;
    #pragma unroll
    for (int it = 0; it < 4; ++it) {
        int idx = it * 256 + t;
        int o = idx >> 4, m4 = idx & 15;
        float4 vr = *(const float4*)(pr + o*64 + m4*4);
        float4 vi = *(const float4*)(pq + o*64 + m4*4);
        smw[o*65 + m4*4+0] = pkbf(vr.x, vi.x);
        smw[o*65 + m4*4+1] = pkbf(vr.y, vi.y);
        smw[o*65 + m4*4+2] = pkbf(vr.z, vi.z);
        smw[o*65 + m4*4+3] = pkbf(vr.w, vi.w);
    }
    __syncthreads();
    #pragma unroll
    for (int it = 0; it < 16; ++it) {
        int idx = it * 256 + t;
        int m = idx >> 6, o = idx & 63;
        g_WtR[((h*64 + m)*64 + i)*64 + o] = smw[o*65 + m];
    }
}

// ===================== unit: Tml gen (32 units) =====================
__device__ void dev_tml(int u, const u32* csb, int t) {
    #pragma unroll
    for (int r = 0; r < 16; ++r) {
        int idx = r*256 + t;
        int mr = u*4 + (idx >> 10), l = idx & 1023;
        int m = mr >> 1;
        u32 v = csb[(m*l) & 1023];
        g_Tml[mr*1024 + l] = ((const bf16*)&v)[mr & 1];
    }
}

// ===================== unit: Tfrag gen (64 units) =====================
__device__ void dev_tfrag(int u, const u32* csb, int t) {
    int idx = u*256 + t;
    int lt = idx >> 11, wid = (idx >> 8) & 7, ks = (idx >> 5) & 7, lane = idx & 31;
    int g = lane >> 2, tig = lane & 3;
    int rr = lt*128 + wid*16 + g;
    int m = ks*8 + tig;
    uint4 v;
    v.x = csb[(m*rr) & 1023];
    v.y = csb[(m*(rr+8)) & 1023];
    v.z = csb[((m+4)*rr) & 1023];
    v.w = csb[((m+4)*(rr+8)) & 1023];
    g_Tfrag[idx] = v;
}

// ===================== unit: stats (512 units, double-buffered) =====================
__device__ void dev_stats(int u, char* dyns, const float* __restrict__ kin,
                          const float* __restrict__ vin, int t) {
    bf16* sV[2]; bf16* sK[2];
    sV[0] = (bf16*)dyns;       sK[0] = sV[0] + 64*SPA;
    sV[1] = sK[0] + 64*SPA;    sK[1] = sV[1] + 64*SPA;
    float* red = (float*)(sK[1] + 64*SPA);   // [256]
    const int bh = u >> 2, ky = u & 3;
    const int b = bh >> 3, h = bh & 7;
    const int wid = t >> 5, lane = t & 31, g = lane >> 2, tig = lane & 3;
    const int ot = wid >> 1, eh = wid & 1;
    const int base = b * NL * HE + h * NE + ky * 256 * HE;
    const int s0 = t >> 6, o0 = t & 63;
    float pk[16], pv[16];
    float ka = 0.f, va = 0.f;

    auto ldg_c = [&](int c) {
        #pragma unroll
        for (int it = 0; it < 16; ++it) {
            int off = base + (c*64 + s0 + it*4)*HE + o0;
            pk[it] = kin[off];
            pv[it] = vin[off];
        }
    };
    auto sts_c = [&](int bi) {
        #pragma unroll
        for (int it = 0; it < 16; ++it) {
            int s = s0 + it*4;
            sK[bi][o0*SPA + s] = __float2bfloat16(pk[it]);
            sV[bi][o0*SPA + s] = __float2bfloat16(pv[it]);
            ka += pk[it]; va += pv[it];
        }
    };

    ldg_c(0);
    sts_c(0);
    ldg_c(1);
    __syncthreads();

    float acc[4][4] = {};
    int p = 0;
    for (int c = 0; c < 4; ++c) {
        #pragma unroll
        for (int ks = 0; ks < 4; ++ks) {
            const int k0 = ks * 16;
            u32 a[4];
            const bf16* ap = sV[p] + (ot*16 + g)*SPA + k0 + tig*2;
            a[0] = *(const u32*)ap;
            a[1] = *(const u32*)(ap + 8*SPA);
            a[2] = *(const u32*)(ap + 8);
            a[3] = *(const u32*)(ap + 8*SPA + 8);
            #pragma unroll
            for (int n = 0; n < 4; ++n) {
                const bf16* bp = sK[p] + (eh*32 + n*8 + g)*SPA + k0 + tig*2;
                u32 bfr[2] = {*(const u32*)bp, *(const u32*)(bp + 8)};
                mma16816(acc[n], a, bfr);
            }
        }
        if (c < 3) {
            sts_c(p ^ 1);
            __syncthreads();
            if (c < 2) ldg_c(c + 2);
            p ^= 1;
        }
    }
    bf16* Mo = g_Mtp + (bh*4 + ky) * 4096;
    const int oo0 = ot*16 + g;
    #pragma unroll
    for (int n = 0; n < 4; ++n) {
        int col = eh*32 + n*8 + tig*2;
        *(u32*)(Mo + oo0*64 + col)     = pkbf(acc[n][0], acc[n][1]);
        *(u32*)(Mo + (oo0+8)*64 + col) = pkbf(acc[n][2], acc[n][3]);
    }
    __syncthreads();
    red[t] = ka; __syncthreads();
    if (t < 64) g_ksp[(bh*4+ky)*64 + t] = red[t] + red[t+64] + red[t+128] + red[t+192];
    __syncthreads();
    red[t] = va; __syncthreads();
    if (t < 64) g_vsp[(bh*4+ky)*64 + t] = red[t] + red[t+64] + red[t+128] + red[t+192];
}

// ===================== unit: forward DFT (512 units, double-buffered, cp.async A) =====================
__device__ void dev_fdft(int u, char* dyns, const float* __restrict__ q, int t) {
    bf16* sA[2]; bf16* sB[2];
    sA[0] = (bf16*)dyns;         sB[0] = sA[0] + 128*SPA;
    sA[1] = sB[0] + 64*SPA;      sB[1] = sA[1] + 128*SPA;
    const int bh = u >> 2, ky = u & 3;
    const int b = bh >> 3, h = bh & 7;
    const int wid = t >> 5, lane = t & 31, g = lane >> 2, tig = lane & 3;
    const int base = b * NL * HE + h * NE;
    const int l00 = t >> 6, e0 = t & 63;
    float pq[16];
    bf16* qbb = g_qb + bh*(NL*NE);

    auto stage_A = [&](int cc, bf16* dst) {
        #pragma unroll
        for (int r = 0; r < 4; ++r) {
            int idx = r*256 + t;
            int row = idx >> 3, w = idx & 7;
            u32 sa = (u32)__cvta_generic_to_shared(dst + row*SPA) + w*16;
            cpa16(sa, (const char*)(g_Tml + row*1024 + cc*64) + w*16);
        }
    };
    auto ldg_c = [&](int c) {
        #pragma unroll
        for (int it = 0; it < 16; ++it)
            pq[it] = q[base + (ky*256 + c*64 + l00 + it*4)*HE + e0];
    };
    auto sts_c = [&](int c, int bi) {
        #pragma unroll
        for (int it = 0; it < 16; ++it) {
            bf16 bv = __float2bfloat16(pq[it]);
            sB[bi][e0*SPA + (l00 + it*4)] = bv;
            qbb[(ky*256 + c*64 + l00 + it*4)*64 + e0] = bv;
        }
    };

    stage_A(ky*4 + 0, sA[0]);
    CPA_COMMIT();
    ldg_c(0);
    sts_c(0, 0);
    ldg_c(1);
    stage_A(ky*4 + 1, sA[1]);
    CPA_COMMIT();
    CPA_WAIT0();                // both sA stages landed (group granularity)
    __syncthreads();

    float acc[8][4] = {};
    int p = 0;
    for (int c = 0; c < 4; ++c) {
        #pragma unroll
        for (int ks = 0; ks < 4; ++ks) {
            const int k0 = ks * 16;
            u32 a[4];
            const bf16* ap = sA[p] + (wid*16 + g)*SPA + k0 + tig*2;
            a[0] = *(const u32*)ap;
            a[1] = *(const u32*)(ap + 8*SPA);
            a[2] = *(const u32*)(ap + 8);
            a[3] = *(const u32*)(ap + 8*SPA + 8);
            #pragma unroll
            for (int n = 0; n < 8; ++n) {
                const bf16* bp = sB[p] + (n*8 + g)*SPA + k0 + tig*2;
                u32 bfr[2] = {*(const u32*)bp, *(const u32*)(bp + 8)};
                mma16816(acc[n], a, bfr);
            }
        }
        if (c < 3) {
            CPA_WAIT0();        // ensure sA[p^1] (for c+1) landed
            sts_c(c + 1, p ^ 1);
            __syncthreads();    // tiles p^1 ready; all warps done reading p
            if (c < 2) {
                ldg_c(c + 2);
                stage_A(ky*4 + c + 2, sA[p]);
                CPA_COMMIT();
            }
            p ^= 1;
        }
    }
    bf16* Xb = g_X + (bh*4 + ky) * 8192;
    const int m0 = wid*16 + g;
    #pragma unroll
    for (int n = 0; n < 8; ++n) {
        int col = n*8 + tig*2;
        *(u32*)(Xb + m0*64 + col)     = pkbf(acc[n][0], acc[n][1]);
        *(u32*)(Xb + (m0+8)*64 + col) = pkbf(acc[n][2], acc[n][3]);
    }
}

// ===================== unit: mix (512 units; Bi frags derived in regs) =====================
__device__ void dev_mix(int u, char* dyns, int t) {
    bf16* sA  = (bf16*)dyns;              // [16][SPB]
    bf16* sBr = sA + 16*SPB;              // [64][SPB]
    const int h = u >> 6, m = u & 63;
    const int wid = t >> 5, lane = t & 31, g = lane >> 2, tig = lane & 3;
    #pragma unroll
    for (int it = 0; it < 4; ++it) {
        int idx = it * 256 + t;
        int bb = idx >> 6, i = idx & 63;
        const bf16* X0 = g_X + ((bb*8 + h)*4)*8192 + (2*m)*64;
        float xc = 0.f, xs = 0.f;
        #pragma unroll
        for (int ky = 0; ky < 4; ++ky) {
            xc += __bfloat162float(X0[ky*8192 + i]);
            xs += __bfloat162float(X0[ky*8192 + 64 + i]);
        }
        *(u32*)&sA[bb*SPB + 2*i] = pkbf(xc, xs);
    }
    const u32* WR = g_WtR + (h*64 + m)*4096;
    #pragma unroll
    for (int it = 0; it < 16; ++it) {
        int idx = it * 256 + t;
        int i = idx >> 6, o = idx & 63;
        *(u32*)&sBr[o*SPB + 2*i] = WR[i*64 + o];
    }
    __syncthreads();
    float acc[2][4] = {};
    const int orow = wid*8 + g;
    #pragma unroll
    for (int ks = 0; ks < 8; ++ks) {
        const int k0 = ks * 16;
        u32 a[4];
        const bf16* ap = &sA[g*SPB + k0 + tig*2];
        a[0] = *(const u32*)ap;
        a[1] = *(const u32*)(ap + 8*SPB);
        a[2] = *(const u32*)(ap + 8);
        a[3] = *(const u32*)(ap + 8*SPB + 8);
        const bf16* brp = &sBr[orow*SPB + k0 + tig*2];
        u32 br[2] = {*(const u32*)brp, *(const u32*)(brp + 8)};
        mma16816(acc[0], a, br);
        // (wi, -wr) frag derived from (wr, wi): swap bf16 halves, flip high sign
        u32 bi2[2] = {__byte_perm(br[0], br[0], 0x1032) ^ 0x80000000u,
                      __byte_perm(br[1], br[1], 0x1032) ^ 0x80000000u};
        mma16816(acc[1], a, bi2);
    }
    const float f = (m == 0 ? 1.0f : 2.0f) * (1.0f / 2048.0f);
    u32* Yt32 = (u32*)g_Yt;
    #pragma unroll
    for (int cc = 0; cc < 2; ++cc) {
        int o = wid*8 + tig*2 + cc;
        Yt32[((g*8 + h)*64 + o)*64 + m]     = pkbf(f*acc[0][cc],   -f*acc[1][cc]);
        Yt32[(((g+8)*8 + h)*64 + o)*64 + m] = pkbf(f*acc[0][cc+2], -f*acc[1][cc+2]);
    }
}

// ===================== unit: merge (128 units) =====================
__device__ void dev_merge(int u, int t) {
    const u32* Mp = (const u32*)(g_Mtp + u*4*4096);
    u32* Mo = (u32*)(g_Mtb + u*4096);
    for (int idx = t; idx < 2048; idx += 256) {
        float sl = 0.f, sh = 0.f;
        #pragma unroll
        for (int ky = 0; ky < 4; ++ky) {
            u32 v = Mp[ky*2048 + idx];
            sl += __bfloat162float(((const bf16*)&v)[0]);
            sh += __bfloat162float(((const bf16*)&v)[1]);
        }
        Mo[idx] = pkbf(sl, sh);
    }
    if (t < 64) {
        const float* kp = g_ksp + u*4*64;
        const float* vp = g_vsp + u*4*64;
        g_ks[u*64 + t] = kp[t] + kp[64+t] + kp[128+t] + kp[192+t];
        g_vs[u*64 + t] = vp[t] + vp[64+t] + vp[128+t] + vp[192+t];
    }
}

// ===================== front kernel: phases 0-2, 3 CTAs/SM =====================
__global__ void __launch_bounds__(256, 3) k_front2(const float* __restrict__ wre,
                                                   const float* __restrict__ wim,
                                                   const float* __restrict__ kin,
                                                   const float* __restrict__ vin,
                                                   const float* __restrict__ q) {
    extern __shared__ char dyns[];
    __shared__ u32 csb[1024];
    __shared__ unsigned s_sense;
    const int t = threadIdx.x;
    const int nb = gridDim.x;
    const int bx = blockIdx.x;

    if (t == 0) s_sense = g_sns;
    #pragma unroll
    for (int r = 0; r < 4; ++r) {
        int j = r*256 + t;
        float s, c;
        sincospif((float)j * (1.0f/512.0f), &s, &c);
        csb[j] = pkbf(c, s);
    }
    __syncthreads();

    auto gridbar = [&]() {
        __threadfence();
        __syncthreads();
        if (t == 0) {
            unsigned s = s_sense ^ 1u;
            s_sense = s;
            unsigned old = atomicAdd(&g_cnt, 1u);
            if (old == (unsigned)nb - 1u) {
                g_cnt = 0;
                __threadfence();
                g_sns = s;
            } else {
                while (g_sns != s) { __nanosleep(64); }
            }
            __threadfence();
        }
        __syncthreads();
    };

    // phase 0: Tml(32) | Tfrag(64)
    for (int u = bx; u < 96; u += nb) {
        if (u < 32) dev_tml(u, csb, t);
        else        dev_tfrag(u - 32, csb, t);
        __syncthreads();
    }
    gridbar();
    // phase 1: wt(512) | stats(512) | fdft(512)
    for (int u = bx; u < 1536; u += nb) {
        if (u < 512)       dev_wt(u, dyns, wre, wim, t);
        else if (u < 1024) dev_stats(u - 512, dyns, kin, vin, t);
        else               dev_fdft(u - 1024, dyns, q, t);
        __syncthreads();
    }
    gridbar();
    // phase 2: mix(512) | merge(128)
    for (int u = bx; u < 640; u += nb) {
        if (u < 512) dev_mix(u, dyns, t);
        else         dev_merge(u - 512, t);
        __syncthreads();
    }
}

// ===================== fused kernel: phase 3, 2 CTAs/SM =====================
__global__ void __launch_bounds__(256, 2) k_fused(float* __restrict__ out) {
    extern __shared__ char dyns[];
    bf16*  sQ0 = (bf16*)(dyns + FQ0_OFF);
    bf16*  sQ1 = (bf16*)(dyns + FQ1_OFF);
    bf16*  sMt = (bf16*)(dyns + FM_OFF);
    bf16*  sY  = (bf16*)(dyns + FY_OFF);
    float* svs = (float*)(dyns + FV_OFF);
    const int bh = blockIdx.x;
    const int half = blockIdx.y;
    const int b = bh >> 3, h = bh & 7;
    const int t = threadIdx.x;
    const int wid = t >> 5, lane = t & 31, g = lane >> 2, tig = lane & 3;
    const bf16* qbb = g_qb + bh*(NL*NE);

    #pragma unroll
    for (int r = 0; r < 2; ++r) {
        int idx = r*256 + t;
        int row = idx >> 3, w = idx & 7;
        u32 sa = (u32)__cvta_generic_to_shared(sMt + row*SPA) + w*16;
        cpa16(sa, (const char*)(g_Mtb + bh*4096 + row*64) + w*16);
    }
    #pragma unroll
    for (int r = 0; r < 4; ++r) {
        int idx = r*256 + t;
        int row = idx >> 4, w = idx & 15;
        u32 sa = (u32)__cvta_generic_to_shared(sY + row*SPB) + w*16;
        cpa16(sa, (const char*)(g_Yt + bh*8192 + row*128) + w*16);
    }
    {
        const int l0 = half * 512;
        #pragma unroll
        for (int r = 0; r < 4; ++r) {
            int idx = r*256 + t;
            int row = idx >> 3, w = idx & 7;
            u32 sa = (u32)__cvta_generic_to_shared(sQ0 + row*SPA) + w*16;
            cpa16(sa, (const char*)(qbb + (l0 + row)*64) + w*16);
        }
    }
    if (t < 64) {
        sMt[64*SPA + t] = __float2bfloat16(g_ks[bh*64 + t]);
        svs[t] = g_vs[bh*64 + t];
    }
    for (int idx = t; idx < 7*SPA; idx += 256)
        sMt[65*SPA + idx] = __float2bfloat16(0.f);
    CPA_COMMIT();
    CPA_WAIT0();
    __syncthreads();

    bf16* sQb[2] = {sQ0, sQ1};
    int p = 0;
    for (int ti = 0; ti < 4; ++ti) {
        const int lt = half*4 + ti;
        const int l0 = lt * 128;
        if (ti < 3) {
            const int l1 = half*512 + (ti+1)*128;
            #pragma unroll
            for (int r = 0; r < 4; ++r) {
                int idx = r*256 + t;
                int row = idx >> 3, w = idx & 7;
                u32 sa = (u32)__cvta_generic_to_shared(sQb[p^1] + row*SPA) + w*16;
                cpa16(sa, (const char*)(qbb + (l1 + row)*64) + w*16);
            }
            CPA_COMMIT();
        }
        const bf16* sQ = sQb[p];
        float accL[9][4] = {};
        float accS[8][4] = {};
        #pragma unroll
        for (int ks = 0; ks < 4; ++ks) {
            const int k0 = ks * 16;
            u32 a[4];
            const bf16* ap = sQ + (wid*16 + g)*SPA + k0 + tig*2;
            a[0] = *(const u32*)ap;
            a[1] = *(const u32*)(ap + 8*SPA);
            a[2] = *(const u32*)(ap + 8);
            a[3] = *(const u32*)(ap + 8*SPA + 8);
            #pragma unroll
            for (int n = 0; n < 9; ++n) {
                const bf16* bp = sMt + (n*8 + g)*SPA + k0 + tig*2;
                u32 bfr[2] = {*(const u32*)bp, *(const u32*)(bp + 8)};
                mma16816(accL[n], a, bfr);
            }
        }
        {
            const uint4* tf = g_Tfrag + ((lt*8 + wid)*8)*32 + lane;
            uint4 av = tf[0];
            #pragma unroll
            for (int ks = 0; ks < 8; ++ks) {
                const int k0 = ks * 16;
                uint4 nv = (ks < 7) ? tf[(ks+1)*32] : av;
                u32 a[4] = {av.x, av.y, av.z, av.w};
                #pragma unroll
                for (int n = 0; n < 8; ++n) {
                    const bf16* bp = sY + (n*8 + g)*SPB + k0 + tig*2;
                    u32 bfr[2] = {*(const u32*)bp, *(const u32*)(bp + 8)};
                    mma16816(accS[n], a, bfr);
                }
                av = nv;
            }
        }
        const int r0 = wid*16 + g;
        float z0 = __shfl_sync(0xffffffffu, accL[8][0], lane & ~3);
        float z1 = __shfl_sync(0xffffffffu, accL[8][2], lane & ~3);
        float inv0 = 0.5f / (1024.0f + SCALE_F * z0);
        float inv1 = 0.5f / (1024.0f + SCALE_F * z1);
        #pragma unroll
        for (int n = 0; n < 8; ++n) {
            int col = n*8 + tig*2;
            float2 o0 = make_float2(
                (svs[col]   + SCALE_F*accL[n][0]) * inv0 + accS[n][0],
                (svs[col+1] + SCALE_F*accL[n][1]) * inv0 + accS[n][1]);
            *(float2*)(out + (b*NL + l0 + r0)*HE + h*NE + col) = o0;
            float2 o1 = make_float2(
                (svs[col]   + SCALE_F*accL[n][2]) * inv1 + accS[n][2],
                (svs[col+1] + SCALE_F*accL[n][3]) * inv1 + accS[n][3]);
            *(float2*)(out + (b*NL + l0 + r0 + 8)*HE + h*NE + col) = o1;
        }
        if (ti < 3) {
            CPA_WAIT0();
            __syncthreads();
            p ^= 1;
        }
    }
}

// ===================== launch =====================
extern "C" void kernel_launch(void* const* d_in, const int* in_sizes, int n_in,
                              void* d_out, int out_size) {
    (void)in_sizes; (void)n_in; (void)out_size;
    const float* q   = (const float*)d_in[0];
    const float* k   = (const float*)d_in[1];
    const float* v   = (const float*)d_in[2];
    // d_in[3] = mask (present -> reference applies no masking); unused
    const float* wre = (const float*)d_in[4];
    const float* wim = (const float*)d_in[5];
    float* out = (float*)d_out;

    static int grid = 0;
    if (!grid) {
        cudaFuncSetAttribute(k_front2, cudaFuncAttributeMaxDynamicSharedMemorySize, FRONT2_SMEM);
        cudaFuncSetAttribute(k_fused,  cudaFuncAttributeMaxDynamicSharedMemorySize, FUSED_SMEM);
        int nsm = 0;
        cudaDeviceGetAttribute(&nsm, cudaDevAttrMultiProcessorCount, 0);
        if (nsm < 1) nsm = 1;
        int occ = 0;
        cudaOccupancyMaxActiveBlocksPerMultiprocessor(&occ, k_front2, 256, FRONT2_SMEM);
        if (occ < 1) occ = 1;
        long g = (long)occ * nsm;          // guaranteed co-resident -> barrier safe
        if (g > 512) g = 512;
        if (g < 1) g = 1;
        grid = (int)g;
    }
    k_front2<<<grid, 256, FRONT2_SMEM>>>(wre, wim, k, v, q);
    k_fused <<<dim3(NBH, 2), 256, FUSED_SMEM>>>(out);
}

// round 17
// speedup vs baseline: 1.2934x; 1.0732x over previous
#include <cuda_runtime.h>
#include <cuda_bf16.h>

#define NB 16
#define NL 1024
#define NH 8
#define NE 64
#define NM 64
#define NBH (NB*NH)
#define HE 512
#define SCALE_F 3.814697265625e-06f  // 1/(512*512)

typedef unsigned long long u64;
typedef unsigned u32;
typedef __nv_bfloat16 bf16;

// -------- scratch (static device globals) --------
static __device__ __align__(16) bf16 g_Mtp[4*NBH*NE*NE];
static __device__ float g_ksp[4*NBH*NE];
static __device__ float g_vsp[4*NBH*NE];
static __device__ __align__(16) bf16 g_X[4*NBH*128*64];
static __device__ __align__(16) bf16 g_Mtb[NBH*NE*NE];
static __device__ float g_ks[NBH*NE];
static __device__ float g_vs[NBH*NE];
static __device__ __align__(16) bf16 g_qb[NBH*NL*NE];
static __device__ __align__(16) bf16 g_Yt[NBH*64*128];
static __device__ __align__(16) bf16 g_Tml[128*1024];
static __device__ uint4 g_Tfrag[8*8*8*32];
static __device__ u32 g_WtR[NH*64*64*64];

// -------- global barrier state --------
static __device__ unsigned g_cnt = 0;
static __device__ volatile unsigned g_sns = 0;

// ---------------- helpers ----------------
__device__ __forceinline__ void mma16816(float* d, const u32* a, const u32* b) {
    asm volatile(
        "mma.sync.aligned.m16n8k16.row.col.f32.bf16.bf16.f32 "
        "{%0,%1,%2,%3}, {%4,%5,%6,%7}, {%8,%9}, {%0,%1,%2,%3};"
        : "+f"(d[0]), "+f"(d[1]), "+f"(d[2]), "+f"(d[3])
        : "r"(a[0]), "r"(a[1]), "r"(a[2]), "r"(a[3]), "r"(b[0]), "r"(b[1]));
}
__device__ __forceinline__ u32 pkbf(float a, float b) {
    __nv_bfloat162 p = __floats2bfloat162_rn(a, b);
    return *(u32*)&p;
}
__device__ __forceinline__ void cpa16(u32 saddr, const void* g) {
    asm volatile("cp.async.cg.shared.global [%0], [%1], 16;" :: "r"(saddr), "l"(g));
}
#define CPA_COMMIT() asm volatile("cp.async.commit_group;" ::: "memory")
#define CPA_WAIT0()  asm volatile("cp.async.wait_group 0;" ::: "memory")

__device__ __forceinline__ u32 s2u(const void* p) {
    return (u32)__cvta_generic_to_shared(p);
}
__device__ __forceinline__ void ldmx4(u32* r, u32 a) {
    asm volatile("ldmatrix.sync.aligned.m8n8.x4.shared.b16 {%0,%1,%2,%3}, [%4];"
                 : "=r"(r[0]), "=r"(r[1]), "=r"(r[2]), "=r"(r[3]) : "r"(a));
}
__device__ __forceinline__ void ldmx2(u32* r, u32 a) {
    asm volatile("ldmatrix.sync.aligned.m8n8.x2.shared.b16 {%0,%1}, [%2];"
                 : "=r"(r[0]), "=r"(r[1]) : "r"(a));
}
// A-frag base addr: tile base, pitch P (bf16), rowbase; add k0*2 bytes per step
__device__ __forceinline__ u32 addrA(const bf16* base, int P, int rowbase, int lane) {
    return s2u(base + (rowbase + (lane & 15)) * P) + (lane & 16);
}
// B pair-frag base addr (two n-frags per ldmx4)
__device__ __forceinline__ u32 addrB(const bf16* base, int P, int nbase, int lane) {
    return s2u(base + (nbase + (lane & 7) + ((lane & 16) >> 1)) * P) + ((lane & 8) << 1);
}

#define SPA 72
#define SPB 136

#define FRONT2_SMEM 55296

#define FQ0_OFF 0
#define FQ1_OFF 18432
#define FM_OFF  36864
#define FY_OFF  47232
#define FV_OFF  64640
#define FUSED_SMEM 64896

// ===================== unit: weight transpose (bf16-packed smem) =====================
__device__ void dev_wt(int u, char* dyns, const float* __restrict__ wre,
                       const float* __restrict__ wim, int t) {
    u32* smw = (u32*)dyns;                // [64][65]
    const int h = u >> 6, i = u & 63;
    const float* pr = wre + (size_t)u * 4096;
    const float* pq = wim + (size_t)u * 4096;
    #pragma unroll
    for (int it = 0; it < 4; ++it) {
        int idx = it * 256 + t;
        int o = idx >> 4, m4 = idx & 15;
        float4 vr = *(const float4*)(pr + o*64 + m4*4);
        float4 vi = *(const float4*)(pq + o*64 + m4*4);
        smw[o*65 + m4*4+0] = pkbf(vr.x, vi.x);
        smw[o*65 + m4*4+1] = pkbf(vr.y, vi.y);
        smw[o*65 + m4*4+2] = pkbf(vr.z, vi.z);
        smw[o*65 + m4*4+3] = pkbf(vr.w, vi.w);
    }
    __syncthreads();
    #pragma unroll
    for (int it = 0; it < 16; ++it) {
        int idx = it * 256 + t;
        int m = idx >> 6, o = idx & 63;
        g_WtR[((h*64 + m)*64 + i)*64 + o] = smw[o*65 + m];
    }
}

// ===================== unit: Tml gen (32 units) =====================
__device__ void dev_tml(int u, const u32* csb, int t) {
    #pragma unroll
    for (int r = 0; r < 16; ++r) {
        int idx = r*256 + t;
        int mr = u*4 + (idx >> 10), l = idx & 1023;
        int m = mr >> 1;
        u32 v = csb[(m*l) & 1023];
        g_Tml[mr*1024 + l] = ((const bf16*)&v)[mr & 1];
    }
}

// ===================== unit: Tfrag gen (64 units) =====================
__device__ void dev_tfrag(int u, const u32* csb, int t) {
    int idx = u*256 + t;
    int lt = idx >> 11, wid = (idx >> 8) & 7, ks = (idx >> 5) & 7, lane = idx & 31;
    int g = lane >> 2, tig = lane & 3;
    int rr = lt*128 + wid*16 + g;
    int m = ks*8 + tig;
    uint4 v;
    v.x = csb[(m*rr) & 1023];
    v.y = csb[(m*(rr+8)) & 1023];
    v.z = csb[((m+4)*rr) & 1023];
    v.w = csb[((m+4)*(rr+8)) & 1023];
    g_Tfrag[idx] = v;
}

// ===================== unit: stats (512 units, double-buffered, ldmatrix) =====================
__device__ void dev_stats(int u, char* dyns, const float* __restrict__ kin,
                          const float* __restrict__ vin, int t) {
    bf16* sV[2]; bf16* sK[2];
    sV[0] = (bf16*)dyns;       sK[0] = sV[0] + 64*SPA;
    sV[1] = sK[0] + 64*SPA;    sK[1] = sV[1] + 64*SPA;
    float* red = (float*)(sK[1] + 64*SPA);
    const int bh = u >> 2, ky = u & 3;
    const int b = bh >> 3, h = bh & 7;
    const int wid = t >> 5, lane = t & 31;
    const int ot = wid >> 1, eh = wid & 1;
    const int base = b * NL * HE + h * NE + ky * 256 * HE;
    const int s0 = t >> 6, o0 = t & 63;
    float pk[16], pv[16];
    float ka = 0.f, va = 0.f;

    auto ldg_c = [&](int c) {
        #pragma unroll
        for (int it = 0; it < 16; ++it) {
            int off = base + (c*64 + s0 + it*4)*HE + o0;
            pk[it] = kin[off];
            pv[it] = vin[off];
        }
    };
    auto sts_c = [&](int bi) {
        #pragma unroll
        for (int it = 0; it < 16; ++it) {
            int s = s0 + it*4;
            sK[bi][o0*SPA + s] = __float2bfloat16(pk[it]);
            sV[bi][o0*SPA + s] = __float2bfloat16(pv[it]);
            ka += pk[it]; va += pv[it];
        }
    };

    ldg_c(0);
    sts_c(0);
    ldg_c(1);
    __syncthreads();

    u32 aV[2], bK0[2], bK1[2];
    #pragma unroll
    for (int bi = 0; bi < 2; ++bi) {
        aV[bi]  = addrA(sV[bi], SPA, ot*16, lane);
        bK0[bi] = addrB(sK[bi], SPA, eh*32, lane);
        bK1[bi] = addrB(sK[bi], SPA, eh*32 + 16, lane);
    }

    float acc[4][4] = {};
    int p = 0;
    for (int c = 0; c < 4; ++c) {
        #pragma unroll
        for (int ks = 0; ks < 4; ++ks) {
            const int kb = ks * 32;
            u32 a[4]; ldmx4(a, aV[p] + kb);
            u32 b01[4]; ldmx4(b01, bK0[p] + kb);
            u32 b23[4]; ldmx4(b23, bK1[p] + kb);
            mma16816(acc[0], a, &b01[0]);
            mma16816(acc[1], a, &b01[2]);
            mma16816(acc[2], a, &b23[0]);
            mma16816(acc[3], a, &b23[2]);
        }
        if (c < 3) {
            sts_c(p ^ 1);
            __syncthreads();
            if (c < 2) ldg_c(c + 2);
            p ^= 1;
        }
    }
    const int g = lane >> 2, tig = lane & 3;
    bf16* Mo = g_Mtp + (bh*4 + ky) * 4096;
    const int oo0 = ot*16 + g;
    #pragma unroll
    for (int n = 0; n < 4; ++n) {
        int col = eh*32 + n*8 + tig*2;
        *(u32*)(Mo + oo0*64 + col)     = pkbf(acc[n][0], acc[n][1]);
        *(u32*)(Mo + (oo0+8)*64 + col) = pkbf(acc[n][2], acc[n][3]);
    }
    __syncthreads();
    red[t] = ka; __syncthreads();
    if (t < 64) g_ksp[(bh*4+ky)*64 + t] = red[t] + red[t+64] + red[t+128] + red[t+192];
    __syncthreads();
    red[t] = va; __syncthreads();
    if (t < 64) g_vsp[(bh*4+ky)*64 + t] = red[t] + red[t+64] + red[t+128] + red[t+192];
}

// ===================== unit: forward DFT (512 units, double-buffered, ldmatrix) =====================
__device__ void dev_fdft(int u, char* dyns, const float* __restrict__ q, int t) {
    bf16* sA[2]; bf16* sB[2];
    sA[0] = (bf16*)dyns;         sB[0] = sA[0] + 128*SPA;
    sA[1] = sB[0] + 64*SPA;      sB[1] = sA[1] + 128*SPA;
    const int bh = u >> 2, ky = u & 3;
    const int b = bh >> 3, h = bh & 7;
    const int wid = t >> 5, lane = t & 31;
    const int base = b * NL * HE + h * NE;
    const int l00 = t >> 6, e0 = t & 63;
    float pq[16];
    bf16* qbb = g_qb + bh*(NL*NE);

    auto stage_A = [&](int cc, bf16* dst) {
        #pragma unroll
        for (int r = 0; r < 4; ++r) {
            int idx = r*256 + t;
            int row = idx >> 3, w = idx & 7;
            u32 sa = s2u(dst + row*SPA) + w*16;
            cpa16(sa, (const char*)(g_Tml + row*1024 + cc*64) + w*16);
        }
    };
    auto ldg_c = [&](int c) {
        #pragma unroll
        for (int it = 0; it < 16; ++it)
            pq[it] = q[base + (ky*256 + c*64 + l00 + it*4)*HE + e0];
    };
    auto sts_c = [&](int c, int bi) {
        #pragma unroll
        for (int it = 0; it < 16; ++it) {
            bf16 bv = __float2bfloat16(pq[it]);
            sB[bi][e0*SPA + (l00 + it*4)] = bv;
            qbb[(ky*256 + c*64 + l00 + it*4)*64 + e0] = bv;
        }
    };

    stage_A(ky*4 + 0, sA[0]);
    CPA_COMMIT();
    ldg_c(0);
    sts_c(0, 0);
    ldg_c(1);
    stage_A(ky*4 + 1, sA[1]);
    CPA_COMMIT();
    CPA_WAIT0();
    __syncthreads();

    u32 aA[2], bB0[2], bB1[2], bB2[2], bB3[2];
    #pragma unroll
    for (int bi = 0; bi < 2; ++bi) {
        aA[bi]  = addrA(sA[bi], SPA, wid*16, lane);
        bB0[bi] = addrB(sB[bi], SPA, 0,  lane);
        bB1[bi] = addrB(sB[bi], SPA, 16, lane);
        bB2[bi] = addrB(sB[bi], SPA, 32, lane);
        bB3[bi] = addrB(sB[bi], SPA, 48, lane);
    }

    float acc[8][4] = {};
    int p = 0;
    for (int c = 0; c < 4; ++c) {
        #pragma unroll
        for (int ks = 0; ks < 4; ++ks) {
            const int kb = ks * 32;
            u32 a[4]; ldmx4(a, aA[p] + kb);
            u32 b0[4]; ldmx4(b0, bB0[p] + kb);
            u32 b1[4]; ldmx4(b1, bB1[p] + kb);
            u32 b2[4]; ldmx4(b2, bB2[p] + kb);
            u32 b3[4]; ldmx4(b3, bB3[p] + kb);
            mma16816(acc[0], a, &b0[0]);
            mma16816(acc[1], a, &b0[2]);
            mma16816(acc[2], a, &b1[0]);
            mma16816(acc[3], a, &b1[2]);
            mma16816(acc[4], a, &b2[0]);
            mma16816(acc[5], a, &b2[2]);
            mma16816(acc[6], a, &b3[0]);
            mma16816(acc[7], a, &b3[2]);
        }
        if (c < 3) {
            CPA_WAIT0();
            sts_c(c + 1, p ^ 1);
            __syncthreads();
            if (c < 2) {
                ldg_c(c + 2);
                stage_A(ky*4 + c + 2, sA[p]);
                CPA_COMMIT();
            }
            p ^= 1;
        }
    }
    const int g = lane >> 2, tig = lane & 3;
    bf16* Xb = g_X + (bh*4 + ky) * 8192;
    const int m0 = wid*16 + g;
    #pragma unroll
    for (int n = 0; n < 8; ++n) {
        int col = n*8 + tig*2;
        *(u32*)(Xb + m0*64 + col)     = pkbf(acc[n][0], acc[n][1]);
        *(u32*)(Xb + (m0+8)*64 + col) = pkbf(acc[n][2], acc[n][3]);
    }
}

// ===================== unit: mix (512 units; ldmatrix; Bi frags derived) =====================
__device__ void dev_mix(int u, char* dyns, int t) {
    bf16* sA  = (bf16*)dyns;              // [16][SPB]
    bf16* sBr = sA + 16*SPB;              // [64][SPB]
    const int h = u >> 6, m = u & 63;
    const int wid = t >> 5, lane = t & 31, g = lane >> 2, tig = lane & 3;
    #pragma unroll
    for (int it = 0; it < 4; ++it) {
        int idx = it * 256 + t;
        int bb = idx >> 6, i = idx & 63;
        const bf16* X0 = g_X + ((bb*8 + h)*4)*8192 + (2*m)*64;
        float xc = 0.f, xs = 0.f;
        #pragma unroll
        for (int ky = 0; ky < 4; ++ky) {
            xc += __bfloat162float(X0[ky*8192 + i]);
            xs += __bfloat162float(X0[ky*8192 + 64 + i]);
        }
        *(u32*)&sA[bb*SPB + 2*i] = pkbf(xc, xs);
    }
    const u32* WR = g_WtR + (h*64 + m)*4096;
    #pragma unroll
    for (int it = 0; it < 16; ++it) {
        int idx = it * 256 + t;
        int i = idx >> 6, o = idx & 63;
        *(u32*)&sBr[o*SPB + 2*i] = WR[i*64 + o];
    }
    __syncthreads();
    const u32 aX = addrA(sA, SPB, 0, lane);
    const u32 bW = addrB(sBr, SPB, wid*8, lane) - ((lane & 16) >> 1) * SPB * 2;
    // ^ x2 uses only lanes 0-15 addressing; mask out the pair-offset for safety
    float acc[2][4] = {};
    #pragma unroll
    for (int ks = 0; ks < 8; ++ks) {
        const int kb = ks * 32;
        u32 a[4]; ldmx4(a, aX + kb);
        u32 br[2]; ldmx2(br, bW + kb);
        mma16816(acc[0], a, br);
        u32 bi2[2] = {__byte_perm(br[0], br[0], 0x1032) ^ 0x80000000u,
                      __byte_perm(br[1], br[1], 0x1032) ^ 0x80000000u};
        mma16816(acc[1], a, bi2);
    }
    const float f = (m == 0 ? 1.0f : 2.0f) * (1.0f / 2048.0f);
    u32* Yt32 = (u32*)g_Yt;
    #pragma unroll
    for (int cc = 0; cc < 2; ++cc) {
        int o = wid*8 + tig*2 + cc;
        Yt32[((g*8 + h)*64 + o)*64 + m]     = pkbf(f*acc[0][cc],   -f*acc[1][cc]);
        Yt32[(((g+8)*8 + h)*64 + o)*64 + m] = pkbf(f*acc[0][cc+2], -f*acc[1][cc+2]);
    }
}

// ===================== unit: merge (128 units) =====================
__device__ void dev_merge(int u, int t) {
    const u32* Mp = (const u32*)(g_Mtp + u*4*4096);
    u32* Mo = (u32*)(g_Mtb + u*4096);
    for (int idx = t; idx < 2048; idx += 256) {
        float sl = 0.f, sh = 0.f;
        #pragma unroll
        for (int ky = 0; ky < 4; ++ky) {
            u32 v = Mp[ky*2048 + idx];
            sl += __bfloat162float(((const bf16*)&v)[0]);
            sh += __bfloat162float(((const bf16*)&v)[1]);
        }
        Mo[idx] = pkbf(sl, sh);
    }
    if (t < 64) {
        const float* kp = g_ksp + u*4*64;
        const float* vp = g_vsp + u*4*64;
        g_ks[u*64 + t] = kp[t] + kp[64+t] + kp[128+t] + kp[192+t];
        g_vs[u*64 + t] = vp[t] + vp[64+t] + vp[128+t] + vp[192+t];
    }
}

// ===================== front kernel: phases 0-2 =====================
__global__ void __launch_bounds__(256, 3) k_front2(const float* __restrict__ wre,
                                                   const float* __restrict__ wim,
                                                   const float* __restrict__ kin,
                                                   const float* __restrict__ vin,
                                                   const float* __restrict__ q) {
    extern __shared__ char dyns[];
    __shared__ u32 csb[1024];
    __shared__ unsigned s_sense;
    const int t = threadIdx.x;
    const int nb = gridDim.x;
    const int bx = blockIdx.x;

    if (t == 0) s_sense = g_sns;
    #pragma unroll
    for (int r = 0; r < 4; ++r) {
        int j = r*256 + t;
        float s, c;
        sincospif((float)j * (1.0f/512.0f), &s, &c);
        csb[j] = pkbf(c, s);
    }
    __syncthreads();

    auto gridbar = [&]() {
        __threadfence();
        __syncthreads();
        if (t == 0) {
            unsigned s = s_sense ^ 1u;
            s_sense = s;
            unsigned old = atomicAdd(&g_cnt, 1u);
            if (old == (unsigned)nb - 1u) {
                g_cnt = 0;
                __threadfence();
                g_sns = s;
            } else {
                while (g_sns != s) { __nanosleep(64); }
            }
            __threadfence();
        }
        __syncthreads();
    };

    for (int u = bx; u < 96; u += nb) {
        if (u < 32) dev_tml(u, csb, t);
        else        dev_tfrag(u - 32, csb, t);
        __syncthreads();
    }
    gridbar();
    for (int u = bx; u < 1536; u += nb) {
        if (u < 512)       dev_wt(u, dyns, wre, wim, t);
        else if (u < 1024) dev_stats(u - 512, dyns, kin, vin, t);
        else               dev_fdft(u - 1024, dyns, q, t);
        __syncthreads();
    }
    gridbar();
    for (int u = bx; u < 640; u += nb) {
        if (u < 512) dev_mix(u, dyns, t);
        else         dev_merge(u - 512, t);
        __syncthreads();
    }
}

// ===================== fused kernel: phase 3 (ldmatrix) =====================
__global__ void __launch_bounds__(256, 2) k_fused(float* __restrict__ out) {
    extern __shared__ char dyns[];
    bf16*  sQ0 = (bf16*)(dyns + FQ0_OFF);
    bf16*  sQ1 = (bf16*)(dyns + FQ1_OFF);
    bf16*  sMt = (bf16*)(dyns + FM_OFF);
    bf16*  sY  = (bf16*)(dyns + FY_OFF);
    float* svs = (float*)(dyns + FV_OFF);
    const int bh = blockIdx.x;
    const int half = blockIdx.y;
    const int b = bh >> 3, h = bh & 7;
    const int t = threadIdx.x;
    const int wid = t >> 5, lane = t & 31, g = lane >> 2, tig = lane & 3;
    const bf16* qbb = g_qb + bh*(NL*NE);

    #pragma unroll
    for (int r = 0; r < 2; ++r) {
        int idx = r*256 + t;
        int row = idx >> 3, w = idx & 7;
        u32 sa = s2u(sMt + row*SPA) + w*16;
        cpa16(sa, (const char*)(g_Mtb + bh*4096 + row*64) + w*16);
    }
    #pragma unroll
    for (int r = 0; r < 4; ++r) {
        int idx = r*256 + t;
        int row = idx >> 4, w = idx & 15;
        u32 sa = s2u(sY + row*SPB) + w*16;
        cpa16(sa, (const char*)(g_Yt + bh*8192 + row*128) + w*16);
    }
    {
        const int l0 = half * 512;
        #pragma unroll
        for (int r = 0; r < 4; ++r) {
            int idx = r*256 + t;
            int row = idx >> 3, w = idx & 7;
            u32 sa = s2u(sQ0 + row*SPA) + w*16;
            cpa16(sa, (const char*)(qbb + (l0 + row)*64) + w*16);
        }
    }
    if (t < 64) {
        sMt[64*SPA + t] = __float2bfloat16(g_ks[bh*64 + t]);
        svs[t] = g_vs[bh*64 + t];
    }
    for (int idx = t; idx < 7*SPA; idx += 256)
        sMt[65*SPA + idx] = __float2bfloat16(0.f);
    CPA_COMMIT();
    CPA_WAIT0();
    __syncthreads();

    const u32 aQ0 = addrA(sQ0, SPA, wid*16, lane);
    const u32 aQ1 = addrA(sQ1, SPA, wid*16, lane);
    u32 bM[4], bM8;
    #pragma unroll
    for (int np = 0; np < 4; ++np) bM[np] = addrB(sMt, SPA, np*16, lane);
    bM8 = addrB(sMt, SPA, 64, lane) - ((lane & 16) >> 1) * SPA * 2;   // x2 form
    u32 bY[4];
    #pragma unroll
    for (int np = 0; np < 4; ++np) bY[np] = addrB(sY, SPB, np*16, lane);

    bf16* sQb[2] = {sQ0, sQ1};
    const u32 aQb[2] = {aQ0, aQ1};
    int p = 0;
    for (int ti = 0; ti < 4; ++ti) {
        const int lt = half*4 + ti;
        const int l0 = lt * 128;
        if (ti < 3) {
            const int l1 = half*512 + (ti+1)*128;
            #pragma unroll
            for (int r = 0; r < 4; ++r) {
                int idx = r*256 + t;
                int row = idx >> 3, w = idx & 7;
                u32 sa = s2u(sQb[p^1] + row*SPA) + w*16;
                cpa16(sa, (const char*)(qbb + (l1 + row)*64) + w*16);
            }
            CPA_COMMIT();
        }
        float accL[9][4] = {};
        float accS[8][4] = {};
        #pragma unroll
        for (int ks = 0; ks < 4; ++ks) {
            const int kb = ks * 32;
            u32 a[4]; ldmx4(a, aQb[p] + kb);
            #pragma unroll
            for (int np = 0; np < 4; ++np) {
                u32 bb[4]; ldmx4(bb, bM[np] + kb);
                mma16816(accL[2*np],     a, &bb[0]);
                mma16816(accL[2*np + 1], a, &bb[2]);
            }
            u32 b8[2]; ldmx2(b8, bM8 + kb);
            mma16816(accL[8], a, b8);
        }
        {
            const uint4* tf = g_Tfrag + ((lt*8 + wid)*8)*32 + lane;
            uint4 av = tf[0];
            #pragma unroll
            for (int ks = 0; ks < 8; ++ks) {
                const int kb = ks * 32;
                uint4 nv = (ks < 7) ? tf[(ks+1)*32] : av;
                u32 a[4] = {av.x, av.y, av.z, av.w};
                #pragma unroll
                for (int np = 0; np < 4; ++np) {
                    u32 bb[4]; ldmx4(bb, bY[np] + kb);
                    mma16816(accS[2*np],     a, &bb[0]);
                    mma16816(accS[2*np + 1], a, &bb[2]);
                }
                av = nv;
            }
        }
        const int r0 = wid*16 + g;
        float z0 = __shfl_sync(0xffffffffu, accL[8][0], lane & ~3);
        float z1 = __shfl_sync(0xffffffffu, accL[8][2], lane & ~3);
        float inv0 = 0.5f / (1024.0f + SCALE_F * z0);
        float inv1 = 0.5f / (1024.0f + SCALE_F * z1);
        #pragma unroll
        for (int n = 0; n < 8; ++n) {
            int col = n*8 + tig*2;
            float2 o0 = make_float2(
                (svs[col]   + SCALE_F*accL[n][0]) * inv0 + accS[n][0],
                (svs[col+1] + SCALE_F*accL[n][1]) * inv0 + accS[n][1]);
            *(float2*)(out + (b*NL + l0 + r0)*HE + h*NE + col) = o0;
            float2 o1 = make_float2(
                (svs[col]   + SCALE_F*accL[n][2]) * inv1 + accS[n][2],
                (svs[col+1] + SCALE_F*accL[n][3]) * inv1 + accS[n][3]);
            *(float2*)(out + (b*NL + l0 + r0 + 8)*HE + h*NE + col) = o1;
        }
        if (ti < 3) {
            CPA_WAIT0();
            __syncthreads();
            p ^= 1;
        }
    }
}

// ===================== launch =====================
extern "C" void kernel_launch(void* const* d_in, const int* in_sizes, int n_in,
                              void* d_out, int out_size) {
    (void)in_sizes; (void)n_in; (void)out_size;
    const float* q   = (const float*)d_in[0];
    const float* k   = (const float*)d_in[1];
    const float* v   = (const float*)d_in[2];
    // d_in[3] = mask (present -> reference applies no masking); unused
    const float* wre = (const float*)d_in[4];
    const float* wim = (const float*)d_in[5];
    float* out = (float*)d_out;

    static int grid = 0;
    if (!grid) {
        cudaFuncSetAttribute(k_front2, cudaFuncAttributeMaxDynamicSharedMemorySize, FRONT2_SMEM);
        cudaFuncSetAttribute(k_fused,  cudaFuncAttributeMaxDynamicSharedMemorySize, FUSED_SMEM);
        int nsm = 0;
        cudaDeviceGetAttribute(&nsm, cudaDevAttrMultiProcessorCount, 0);
        if (nsm < 1) nsm = 1;
        int occ = 0;
        cudaOccupancyMaxActiveBlocksPerMultiprocessor(&occ, k_front2, 256, FRONT2_SMEM);
        if (occ < 1) occ = 1;
        long g = (long)occ * nsm;
        if (g > 512) g = 512;
        if (g < 1) g = 1;
        grid = (int)g;
    }
    k_front2<<<grid, 256, FRONT2_SMEM>>>(wre, wim, k, v, q);
    k_fused <<<dim3(NBH, 2), 256, FUSED_SMEM>>>(out);
}